// round 4
// baseline (speedup 1.0000x reference)
#include <cuda_runtime.h>
#include <cuda_bf16.h>
#include <cstdint>

// ---------------------------------------------------------------------------
// Shapes (fixed by the problem)
// ---------------------------------------------------------------------------
#define B_  16
#define N_  4096
#define C_  768
#define L_  16
#define H_  12
#define HD_ 64
#define STEPS_ 3
#define BH_ (B_ * H_)               // 192

#define MROWS_ (B_ * N_)            // 65536
#define KSEG_  3                    // hi*hi, hi*lo, lo*hi
#define BK_    32                   // k per pipeline chunk
#define CH_PER_SEG_ (C_ / BK_)      // 24
#define NCHUNK_TOT_ (KSEG_ * CH_PER_SEG_)  // 72

// Hopfield split
#define TN_ 128
#define NWARP_ 8
#define NS_ 4
#define NT_SPL_ (N_ / NS_ / TN_)    // 8 tiles per split

// ---------------------------------------------------------------------------
// Scratch (__device__ globals — no allocation allowed in kernel_launch)
// ---------------------------------------------------------------------------
__device__ __align__(16) float g_k_scr[(size_t)MROWS_ * C_];       // k = x @ Wk^T
__device__ __align__(16) __nv_bfloat16 g_xh[(size_t)MROWS_ * C_];
__device__ __align__(16) __nv_bfloat16 g_xl[(size_t)MROWS_ * C_];
__device__ __align__(16) __nv_bfloat16 g_wh[(size_t)C_ * C_];
__device__ __align__(16) __nv_bfloat16 g_wl[(size_t)C_ * C_];
__device__ float g_q0_scr[L_ * C_];
__device__ float g_qf_scr[B_ * L_ * C_];
__device__ float g_tmp_scr[B_ * L_ * C_];
__device__ __align__(16) float g_q_state[BH_ * L_ * HD_];
__device__ float g_m_part[BH_ * NS_ * L_];
__device__ float g_z_part[BH_ * NS_ * L_];
__device__ __align__(16) float g_acc_part[(size_t)BH_ * NS_ * L_ * HD_];

// ---------------------------------------------------------------------------
// helpers
// ---------------------------------------------------------------------------
__device__ __forceinline__ uint32_t smem_u32(const void* p) {
    uint32_t a;
    asm("{ .reg .u64 t; cvta.to.shared.u64 t, %1; cvt.u32.u64 %0, t; }" : "=r"(a) : "l"(p));
    return a;
}
__device__ __forceinline__ void cpa16(uint32_t dst, const void* src) {
    asm volatile("cp.async.cg.shared.global [%0], [%1], 16;" :: "r"(dst), "l"(src));
}
#define CP_COMMIT() asm volatile("cp.async.commit_group;" ::: "memory")
#define CP_WAIT1()  asm volatile("cp.async.wait_group 1;" ::: "memory")
#define CP_WAIT0()  asm volatile("cp.async.wait_group 0;" ::: "memory")

__device__ __forceinline__ void ldsm_x4(uint32_t* r, uint32_t addr) {
    asm volatile("ldmatrix.sync.aligned.m8n8.x4.shared.b16 {%0,%1,%2,%3}, [%4];"
                 : "=r"(r[0]), "=r"(r[1]), "=r"(r[2]), "=r"(r[3]) : "r"(addr));
}
__device__ __forceinline__ void ldsm_x2(uint32_t* r, uint32_t addr) {
    asm volatile("ldmatrix.sync.aligned.m8n8.x2.shared.b16 {%0,%1}, [%2];"
                 : "=r"(r[0]), "=r"(r[1]) : "r"(addr));
}
__device__ __forceinline__ void mma_bf16(float* d, const uint32_t* a, const uint32_t* b) {
    asm volatile(
        "mma.sync.aligned.m16n8k16.row.col.f32.bf16.bf16.f32 "
        "{%0,%1,%2,%3}, {%4,%5,%6,%7}, {%8,%9}, {%0,%1,%2,%3};"
        : "+f"(d[0]), "+f"(d[1]), "+f"(d[2]), "+f"(d[3])
        : "r"(a[0]), "r"(a[1]), "r"(a[2]), "r"(a[3]), "r"(b[0]), "r"(b[1]));
}

// ---------------------------------------------------------------------------
// Kernel A: split fp32 -> (hi, lo) bf16, plain row-major
// ---------------------------------------------------------------------------
__global__ void __launch_bounds__(256) convert_split_kernel(
    const float* __restrict__ src, __nv_bfloat16* __restrict__ hi,
    __nv_bfloat16* __restrict__ lo, int nchunks)
{
    int idx = blockIdx.x * 256 + threadIdx.x;
    if (idx >= nchunks) return;
    size_t e = (size_t)idx * 8;

    const float4* p = (const float4*)(src + e);
    float4 a = p[0], b = p[1];
    float v[8] = {a.x, a.y, a.z, a.w, b.x, b.y, b.z, b.w};

    uint32_t hp[4], lp[4];
#pragma unroll
    for (int i = 0; i < 4; i++) {
        __nv_bfloat16 h0 = __float2bfloat16(v[2*i]);
        __nv_bfloat16 h1 = __float2bfloat16(v[2*i+1]);
        __nv_bfloat16 l0 = __float2bfloat16(v[2*i]   - __bfloat162float(h0));
        __nv_bfloat16 l1 = __float2bfloat16(v[2*i+1] - __bfloat162float(h1));
        hp[i] = (uint32_t)__bfloat16_as_ushort(h0) | ((uint32_t)__bfloat16_as_ushort(h1) << 16);
        lp[i] = (uint32_t)__bfloat16_as_ushort(l0) | ((uint32_t)__bfloat16_as_ushort(l1) << 16);
    }
    *(uint4*)(hi + e) = make_uint4(hp[0], hp[1], hp[2], hp[3]);
    *(uint4*)(lo + e) = make_uint4(lp[0], lp[1], lp[2], lp[3]);
}

// ---------------------------------------------------------------------------
// Kernel B: HMMA GEMM  out[65536, 768] = Xsplit @ Wsplit^T  (K = 3*768)
// CTA 128x128, 8 warps of 64x32, BK=32, 3-stage cp.async, 2 CTAs/SM.
// ---------------------------------------------------------------------------
#define ROWB_ 80
#define TILEB_ (128 * ROWB_)
#define STAGEB_ (2 * TILEB_)
#define NSTG_ 3
#define GEMM_SMEM_REQ (NSTG_ * STAGEB_)  // 61440

__device__ __forceinline__ void load_tile(
    uint32_t aS, uint32_t bS, const char* Aseg, const char* Bseg,
    int mt, int nt, int kk, int tid)
{
#pragma unroll
    for (int i = 0; i < 2; i++) {
        int idx = tid + i * 256;
        int row = idx >> 2, c = idx & 3;
        cpa16(aS + row * ROWB_ + c * 16,
              Aseg + ((size_t)(mt * 128 + row) * C_ + kk + c * 8) * 2);
    }
#pragma unroll
    for (int i = 0; i < 2; i++) {
        int idx = tid + i * 256;
        int row = idx >> 2, c = idx & 3;
        cpa16(bS + row * ROWB_ + c * 16,
              Bseg + ((size_t)(nt * 128 + row) * C_ + kk + c * 8) * 2);
    }
}

__global__ void __launch_bounds__(256, 2) k_gemm_mma(
    const __nv_bfloat16* __restrict__ xh, const __nv_bfloat16* __restrict__ xl,
    const __nv_bfloat16* __restrict__ wh, const __nv_bfloat16* __restrict__ wl,
    float* __restrict__ out)
{
    extern __shared__ char dsm[];
    const uint32_t sbase = smem_u32(dsm);

    const int tid  = threadIdx.x;
    const int lane = tid & 31;
    const int warp = tid >> 5;
    const int wm   = warp >> 2;
    const int wn   = warp & 3;
    const int nt   = blockIdx.x;
    const int mt   = blockIdx.y;

    const char* Asrc[KSEG_] = {(const char*)xh, (const char*)xh, (const char*)xl};
    const char* Bsrc[KSEG_] = {(const char*)wh, (const char*)wl, (const char*)wh};

    float acc[4][4][4];
#pragma unroll
    for (int mi = 0; mi < 4; mi++)
#pragma unroll
        for (int ni = 0; ni < 4; ni++)
#pragma unroll
            for (int i = 0; i < 4; i++) acc[mi][ni][i] = 0.0f;

#pragma unroll
    for (int s = 0; s < NSTG_ - 1; s++) {
        load_tile(sbase + s * STAGEB_, sbase + s * STAGEB_ + TILEB_,
                  Asrc[0], Bsrc[0], mt, nt, s * BK_, tid);
        CP_COMMIT();
    }

    const uint32_t a_lane_off = (uint32_t)((lane & 15) * ROWB_ + (lane >> 4) * 16);
    const uint32_t b_lane_off = (uint32_t)((lane & 7) * ROWB_ + ((lane >> 3) & 1) * 16);

    for (int kc = 0; kc < NCHUNK_TOT_; kc++) {
        CP_WAIT1();
        __syncthreads();

        int pf = kc + NSTG_ - 1;
        if (pf < NCHUNK_TOT_) {
            int seg = pf / CH_PER_SEG_;
            int kk  = (pf % CH_PER_SEG_) * BK_;
            int s   = pf % NSTG_;
            load_tile(sbase + s * STAGEB_, sbase + s * STAGEB_ + TILEB_,
                      Asrc[seg], Bsrc[seg], mt, nt, kk, tid);
        }
        CP_COMMIT();

        const uint32_t aS = sbase + (kc % NSTG_) * STAGEB_;
        const uint32_t bS = aS + TILEB_;
#pragma unroll
        for (int h = 0; h < 2; h++) {
            uint32_t a[4][4], b[4][2];
#pragma unroll
            for (int mi = 0; mi < 4; mi++)
                ldsm_x4(a[mi], aS + (wm * 64 + mi * 16) * ROWB_ + h * 32 + a_lane_off);
#pragma unroll
            for (int ni = 0; ni < 4; ni++)
                ldsm_x2(b[ni], bS + (wn * 32 + ni * 8) * ROWB_ + h * 32 + b_lane_off);
#pragma unroll
            for (int mi = 0; mi < 4; mi++)
#pragma unroll
                for (int ni = 0; ni < 4; ni++)
                    mma_bf16(acc[mi][ni], a[mi], b[ni]);
        }
        __syncthreads();
    }

#pragma unroll
    for (int mi = 0; mi < 4; mi++) {
#pragma unroll
        for (int ni = 0; ni < 4; ni++) {
            int r = mt * 128 + wm * 64 + mi * 16 + (lane >> 2);
            int c = nt * 128 + wn * 32 + ni * 8 + (lane & 3) * 2;
            float2 v0 = make_float2(acc[mi][ni][0], acc[mi][ni][1]);
            float2 v1 = make_float2(acc[mi][ni][2], acc[mi][ni][3]);
            *(float2*)&out[(size_t)r * C_ + c] = v0;
            *(float2*)&out[(size_t)(r + 8) * C_ + c] = v1;
        }
    }
}

// ---------------------------------------------------------------------------
// Kernel 2: small GEMM  C[M,N] = A[M,K]*B[N,K]^T (+bias)
// ---------------------------------------------------------------------------
__global__ void __launch_bounds__(256) small_gemm_nt(
    const float* __restrict__ A, const float* __restrict__ Bm,
    const float* __restrict__ bias, float* __restrict__ C,
    int M, int N, int K)
{
    __shared__ float AsT[16][17];
    __shared__ float BsT[16][65];

    const int t  = threadIdx.x;
    const int n0 = blockIdx.x * 64;
    const int m0 = blockIdx.y * 16;
    const int r0 = t >> 6;
    const int c  = t & 63;

    float acc[4] = {0.f, 0.f, 0.f, 0.f};

    for (int k0 = 0; k0 < K; k0 += 16) {
        __syncthreads();
        { int mm = t >> 4, kk = t & 15;
          AsT[kk][mm] = A[(long)(m0 + mm) * K + k0 + kk]; }
        { int nn = t >> 2, k4 = (t & 3) * 4;
          float4 v = *(const float4*)&Bm[(long)(n0 + nn) * K + k0 + k4];
          BsT[k4 + 0][nn] = v.x; BsT[k4 + 1][nn] = v.y;
          BsT[k4 + 2][nn] = v.z; BsT[k4 + 3][nn] = v.w; }
        __syncthreads();
#pragma unroll
        for (int kk = 0; kk < 16; kk++) {
            float bb = BsT[kk][c];
            acc[0] = fmaf(AsT[kk][r0 +  0], bb, acc[0]);
            acc[1] = fmaf(AsT[kk][r0 +  4], bb, acc[1]);
            acc[2] = fmaf(AsT[kk][r0 +  8], bb, acc[2]);
            acc[3] = fmaf(AsT[kk][r0 + 12], bb, acc[3]);
        }
    }
    float bv = bias ? bias[n0 + c] : 0.0f;
#pragma unroll
    for (int i = 0; i < 4; i++)
        C[(long)(m0 + r0 + 4 * i) * N + n0 + c] = acc[i] + bv;
}

// ---------------------------------------------------------------------------
// Hopfield step, split-N version.
//   hop_init_q: q_state[bh] <- q0 (broadcast over batch)
//   hop_partial: per (split, bh): flash partial over 1024 keys -> m, Z, acc
//   hop_combine: reduce NS_ partials, apply softmax_1 (clamp 0, +exp(-M)), div
// ---------------------------------------------------------------------------
__global__ void hop_init_q(const float* __restrict__ q0, float* __restrict__ qst)
{
    int bh = blockIdx.x, h = bh % H_;
    for (int i = threadIdx.x; i < L_ * HD_; i += 256) {
        int l = i >> 6, d = i & 63;
        qst[bh * (L_ * HD_) + i] = q0[l * C_ + h * HD_ + d];
    }
}

#define HOP_SMEM_ (2 * TN_ * HD_ * 4)   // 65536 B double buffer

__global__ void __launch_bounds__(256, 2) hop_partial(
    const float* __restrict__ qst, const float* __restrict__ kmat,
    float* __restrict__ m_part, float* __restrict__ z_part,
    float* __restrict__ acc_part)
{
    extern __shared__ __align__(16) float hsm[];  // [2][TN_*HD_]
    __shared__ float mw[NWARP_][L_];
    __shared__ float zw[NWARP_][L_];
    __shared__ float Mg[L_];

    const int t     = threadIdx.x;
    const int warp  = t >> 5;
    const int lane  = t & 31;
    const int split = blockIdx.x;
    const int bh    = blockIdx.y;
    const int b     = bh / H_;
    const int h     = bh % H_;
    const int l     = lane >> 1;
    const int dbase = (lane & 1) * 32;
    const float scale = 0.125f;

    const char* kbase = (const char*)(kmat + (size_t)b * N_ * C_ + h * HD_
                                      + (size_t)(split * (N_ / NS_)) * C_);
    const uint32_t sb = smem_u32(hsm);

    // q registers (pre-scaled)
    float qreg[32];
    {
        const float4* qp = (const float4*)(qst + bh * (L_ * HD_) + l * HD_ + dbase);
#pragma unroll
        for (int i = 0; i < 8; i++) {
            float4 v = qp[i];
            qreg[i*4+0] = v.x * scale; qreg[i*4+1] = v.y * scale;
            qreg[i*4+2] = v.z * scale; qreg[i*4+3] = v.w * scale;
        }
    }
    float m = -1e30f, Z = 0.0f;
    float acc[32];
#pragma unroll
    for (int i = 0; i < 32; i++) acc[i] = 0.0f;

    // prefetch tile 0
    {
#pragma unroll
        for (int i = 0; i < 8; i++) {
            int idx = t + i * 256;
            int row = idx >> 4, c = idx & 15;
            cpa16(sb + row * 256 + c * 16, kbase + (size_t)row * (C_ * 4) + c * 16);
        }
        CP_COMMIT();
    }

    for (int tile = 0; tile < NT_SPL_; tile++) {
        if (tile + 1 < NT_SPL_) {
            uint32_t dst = sb + ((tile + 1) & 1) * (TN_ * HD_ * 4);
            const char* src = kbase + (size_t)(tile + 1) * TN_ * (C_ * 4);
#pragma unroll
            for (int i = 0; i < 8; i++) {
                int idx = t + i * 256;
                int row = idx >> 4, c = idx & 15;
                cpa16(dst + row * 256 + c * 16, src + (size_t)row * (C_ * 4) + c * 16);
            }
            CP_COMMIT();
            CP_WAIT1();
        } else {
            CP_WAIT0();
        }
        __syncthreads();

        const float* buf = hsm + (tile & 1) * (TN_ * HD_);

        float s[16];
#pragma unroll
        for (int jj = 0; jj < 16; jj++) {
            const float* kp = &buf[(warp * 16 + jj) * HD_ + dbase];
            float partial = 0.0f;
#pragma unroll
            for (int i = 0; i < 8; i++) {
                float4 kv = *(const float4*)&kp[i * 4];
                partial = fmaf(qreg[i*4+0], kv.x, partial);
                partial = fmaf(qreg[i*4+1], kv.y, partial);
                partial = fmaf(qreg[i*4+2], kv.z, partial);
                partial = fmaf(qreg[i*4+3], kv.w, partial);
            }
            s[jj] = partial + __shfl_xor_sync(0xffffffffu, partial, 1);
        }
        float tm = s[0];
#pragma unroll
        for (int jj = 1; jj < 16; jj++) tm = fmaxf(tm, s[jj]);
        float Mn = fmaxf(m, tm);
        float sc = __expf(m - Mn);
        Z *= sc;
#pragma unroll
        for (int i = 0; i < 32; i++) acc[i] *= sc;
#pragma unroll
        for (int jj = 0; jj < 16; jj++) {
            float p = __expf(s[jj] - Mn);
            Z += p;
            const float* kp = &buf[(warp * 16 + jj) * HD_ + dbase];
#pragma unroll
            for (int i = 0; i < 8; i++) {
                float4 kv = *(const float4*)&kp[i * 4];
                acc[i*4+0] = fmaf(p, kv.x, acc[i*4+0]);
                acc[i*4+1] = fmaf(p, kv.y, acc[i*4+1]);
                acc[i*4+2] = fmaf(p, kv.z, acc[i*4+2]);
                acc[i*4+3] = fmaf(p, kv.w, acc[i*4+3]);
            }
        }
        m = Mn;
        __syncthreads();
    }

    // block-level combine (NO clamp / NO +exp(-M) here — that's global)
    if ((lane & 1) == 0) { mw[warp][l] = m; zw[warp][l] = Z; }
    __syncthreads();
    if (t < L_) {
        float M = -1e30f;
#pragma unroll
        for (int w = 0; w < NWARP_; w++) M = fmaxf(M, mw[w][t]);
        Mg[t] = M;
        float Zt = 0.0f;
#pragma unroll
        for (int w = 0; w < NWARP_; w++)
            Zt += zw[w][t] * __expf(mw[w][t] - M);
        int o = (bh * NS_ + split) * L_ + t;
        m_part[o] = M;
        z_part[o] = Zt;
    }
    __syncthreads();
    {
        float f = __expf(m - Mg[l]);
#pragma unroll
        for (int i = 0; i < 8; i++) {
            float4 v = make_float4(acc[i*4+0]*f, acc[i*4+1]*f,
                                   acc[i*4+2]*f, acc[i*4+3]*f);
            *(float4*)&hsm[warp * (L_ * HD_) + l * HD_ + dbase + i * 4] = v;
        }
    }
    __syncthreads();
    size_t ob = (size_t)(bh * NS_ + split) * (L_ * HD_);
    for (int i = t; i < L_ * HD_; i += 256) {
        float sum = 0.0f;
#pragma unroll
        for (int w = 0; w < NWARP_; w++) sum += hsm[w * (L_ * HD_) + i];
        acc_part[ob + i] = sum;
    }
}

__global__ void hop_combine(
    const float* __restrict__ m_part, const float* __restrict__ z_part,
    const float* __restrict__ acc_part, float* __restrict__ qdst, int final_mode)
{
    __shared__ float F[NS_][L_];
    __shared__ float Zs[L_];

    const int bh = blockIdx.x;
    const int b = bh / H_, h = bh % H_;
    const int t = threadIdx.x;

    if (t < L_) {
        float mv[NS_];
        float M = 0.0f;   // softmax_1 clamp at 0
#pragma unroll
        for (int i = 0; i < NS_; i++) {
            mv[i] = m_part[(bh * NS_ + i) * L_ + t];
            M = fmaxf(M, mv[i]);
        }
        float Zt = __expf(-M);   // phantom logit 0
#pragma unroll
        for (int i = 0; i < NS_; i++) {
            float f = __expf(mv[i] - M);
            F[i][t] = f;
            Zt += z_part[(bh * NS_ + i) * L_ + t] * f;
        }
        Zs[t] = Zt;
    }
    __syncthreads();

    for (int idx = t; idx < L_ * HD_; idx += 256) {
        int l = idx >> 6, d = idx & 63;
        float sum = 0.0f;
#pragma unroll
        for (int i = 0; i < NS_; i++)
            sum += acc_part[(size_t)(bh * NS_ + i) * (L_ * HD_) + idx] * F[i][l];
        sum /= Zs[l];
        if (final_mode)
            qdst[((size_t)b * L_ + l) * C_ + h * HD_ + d] = sum;
        else
            qdst[bh * (L_ * HD_) + idx] = sum;
    }
}

// ---------------------------------------------------------------------------
// Launch
// ---------------------------------------------------------------------------
extern "C" void kernel_launch(void* const* d_in, const int* in_sizes, int n_in,
                              void* d_out, int out_size)
{
    const float* x     = (const float*)d_in[0];
    const float* query = (const float*)d_in[1];
    const float* Wq    = (const float*)d_in[2];
    const float* Wk    = (const float*)d_in[3];
    const float* Wv    = (const float*)d_in[4];
    const float* Wproj = (const float*)d_in[5];
    const float* bproj = (const float*)d_in[6];
    float* out = (float*)d_out;

    float *k_scr, *q0_scr, *qf_scr, *tmp_scr, *q_state, *m_part, *z_part, *acc_part;
    __nv_bfloat16 *xh, *xl, *wh, *wl;
    cudaGetSymbolAddress((void**)&k_scr,  g_k_scr);
    cudaGetSymbolAddress((void**)&q0_scr, g_q0_scr);
    cudaGetSymbolAddress((void**)&qf_scr, g_qf_scr);
    cudaGetSymbolAddress((void**)&tmp_scr, g_tmp_scr);
    cudaGetSymbolAddress((void**)&q_state, g_q_state);
    cudaGetSymbolAddress((void**)&m_part, g_m_part);
    cudaGetSymbolAddress((void**)&z_part, g_z_part);
    cudaGetSymbolAddress((void**)&acc_part, g_acc_part);
    cudaGetSymbolAddress((void**)&xh, g_xh);
    cudaGetSymbolAddress((void**)&xl, g_xl);
    cudaGetSymbolAddress((void**)&wh, g_wh);
    cudaGetSymbolAddress((void**)&wl, g_wl);

    static bool attr_set = false;
    if (!attr_set) {
        cudaFuncSetAttribute(k_gemm_mma, cudaFuncAttributeMaxDynamicSharedMemorySize,
                             GEMM_SMEM_REQ);
        cudaFuncSetAttribute(hop_partial, cudaFuncAttributeMaxDynamicSharedMemorySize,
                             HOP_SMEM_);
        attr_set = true;
    }

    // split/convert x and Wk into row-major bf16 hi/lo
    {
        int nch_x = (MROWS_ * C_) / 8;
        convert_split_kernel<<<(nch_x + 255) / 256, 256>>>(x, xh, xl, nch_x);
        int nch_w = (C_ * C_) / 8;
        convert_split_kernel<<<(nch_w + 255) / 256, 256>>>(Wk, wh, wl, nch_w);
    }
    // q0 = query @ Wq^T
    small_gemm_nt<<<dim3(C_ / 64, 1), 256>>>(query, Wq, nullptr, q0_scr, L_, C_, C_);
    // k = x @ Wk^T via HMMA (3-term bf16 split)
    k_gemm_mma<<<dim3(C_ / 128, MROWS_ / 128), 256, GEMM_SMEM_REQ>>>(xh, xl, wh, wl, k_scr);
    // 3-step Hopfield attention, split-N
    hop_init_q<<<BH_, 256>>>(q0_scr, q_state);
    for (int s = 0; s < STEPS_; s++) {
        hop_partial<<<dim3(NS_, BH_), 256, HOP_SMEM_>>>(
            q_state, k_scr, m_part, z_part, acc_part);
        hop_combine<<<BH_, 256>>>(m_part, z_part, acc_part,
                                  (s == STEPS_ - 1) ? qf_scr : q_state,
                                  (s == STEPS_ - 1) ? 1 : 0);
    }
    // out projections
    small_gemm_nt<<<dim3(C_ / 64, (B_ * L_) / 16), 256>>>(
        qf_scr, Wv, nullptr, tmp_scr, B_ * L_, C_, C_);
    small_gemm_nt<<<dim3(C_ / 64, (B_ * L_) / 16), 256>>>(
        tmp_scr, Wproj, bproj, out, B_ * L_, C_, C_);
}

// round 5
// speedup vs baseline: 1.0177x; 1.0177x over previous
#include <cuda_runtime.h>
#include <cuda_bf16.h>
#include <cstdint>

// ---------------------------------------------------------------------------
// Shapes (fixed by the problem)
// ---------------------------------------------------------------------------
#define B_  16
#define N_  4096
#define C_  768
#define L_  16
#define H_  12
#define HD_ 64
#define STEPS_ 3
#define BH_ (B_ * H_)               // 192

#define MROWS_ (B_ * N_)            // 65536
#define KSEG_  3                    // hi*hi, hi*lo, lo*hi
#define BK_    32
#define CH_PER_SEG_ (C_ / BK_)      // 24
#define NCHUNK_TOT_ (KSEG_ * CH_PER_SEG_)  // 72

// Hopfield split
#define TN_ 128
#define NWARP_ 8
#define NS_ 4
#define NT_SPL_ (N_ / NS_ / TN_)    // 8 tiles per split

// ---------------------------------------------------------------------------
// Scratch (__device__ globals — no allocation allowed in kernel_launch)
// k scratch layout: HEAD-MAJOR [B, H, N, 64]  (contiguous per (b,h))
// ---------------------------------------------------------------------------
__device__ __align__(16) float g_k_scr[(size_t)MROWS_ * C_];
__device__ __align__(16) __nv_bfloat16 g_xh[(size_t)MROWS_ * C_];
__device__ __align__(16) __nv_bfloat16 g_xl[(size_t)MROWS_ * C_];
__device__ __align__(16) __nv_bfloat16 g_wh[(size_t)C_ * C_];
__device__ __align__(16) __nv_bfloat16 g_wl[(size_t)C_ * C_];
__device__ float g_q0_scr[L_ * C_];
__device__ float g_qf_scr[B_ * L_ * C_];
__device__ float g_tmp_scr[B_ * L_ * C_];
__device__ __align__(16) float g_q_state[BH_ * L_ * HD_];
__device__ float g_m_part[BH_ * NS_ * L_];
__device__ float g_z_part[BH_ * NS_ * L_];
__device__ __align__(16) float g_acc_part[(size_t)BH_ * NS_ * L_ * HD_];

// ---------------------------------------------------------------------------
// helpers
// ---------------------------------------------------------------------------
__device__ __forceinline__ uint32_t smem_u32(const void* p) {
    uint32_t a;
    asm("{ .reg .u64 t; cvta.to.shared.u64 t, %1; cvt.u32.u64 %0, t; }" : "=r"(a) : "l"(p));
    return a;
}
__device__ __forceinline__ void cpa16(uint32_t dst, const void* src) {
    asm volatile("cp.async.cg.shared.global [%0], [%1], 16;" :: "r"(dst), "l"(src));
}
#define CP_COMMIT() asm volatile("cp.async.commit_group;" ::: "memory")
#define CP_WAIT1()  asm volatile("cp.async.wait_group 1;" ::: "memory")
#define CP_WAIT0()  asm volatile("cp.async.wait_group 0;" ::: "memory")

__device__ __forceinline__ void ldsm_x4(uint32_t* r, uint32_t addr) {
    asm volatile("ldmatrix.sync.aligned.m8n8.x4.shared.b16 {%0,%1,%2,%3}, [%4];"
                 : "=r"(r[0]), "=r"(r[1]), "=r"(r[2]), "=r"(r[3]) : "r"(addr));
}
__device__ __forceinline__ void ldsm_x2(uint32_t* r, uint32_t addr) {
    asm volatile("ldmatrix.sync.aligned.m8n8.x2.shared.b16 {%0,%1}, [%2];"
                 : "=r"(r[0]), "=r"(r[1]) : "r"(addr));
}
__device__ __forceinline__ void mma_bf16(float* d, const uint32_t* a, const uint32_t* b) {
    asm volatile(
        "mma.sync.aligned.m16n8k16.row.col.f32.bf16.bf16.f32 "
        "{%0,%1,%2,%3}, {%4,%5,%6,%7}, {%8,%9}, {%0,%1,%2,%3};"
        : "+f"(d[0]), "+f"(d[1]), "+f"(d[2]), "+f"(d[3])
        : "r"(a[0]), "r"(a[1]), "r"(a[2]), "r"(a[3]), "r"(b[0]), "r"(b[1]));
}

// ---------------------------------------------------------------------------
// Kernel A: split fp32 -> (hi, lo) bf16, plain row-major
// ---------------------------------------------------------------------------
__global__ void __launch_bounds__(256) convert_split_kernel(
    const float* __restrict__ src, __nv_bfloat16* __restrict__ hi,
    __nv_bfloat16* __restrict__ lo, int nchunks)
{
    int idx = blockIdx.x * 256 + threadIdx.x;
    if (idx >= nchunks) return;
    size_t e = (size_t)idx * 8;

    const float4* p = (const float4*)(src + e);
    float4 a = p[0], b = p[1];
    float v[8] = {a.x, a.y, a.z, a.w, b.x, b.y, b.z, b.w};

    uint32_t hp[4], lp[4];
#pragma unroll
    for (int i = 0; i < 4; i++) {
        __nv_bfloat16 h0 = __float2bfloat16(v[2*i]);
        __nv_bfloat16 h1 = __float2bfloat16(v[2*i+1]);
        __nv_bfloat16 l0 = __float2bfloat16(v[2*i]   - __bfloat162float(h0));
        __nv_bfloat16 l1 = __float2bfloat16(v[2*i+1] - __bfloat162float(h1));
        hp[i] = (uint32_t)__bfloat16_as_ushort(h0) | ((uint32_t)__bfloat16_as_ushort(h1) << 16);
        lp[i] = (uint32_t)__bfloat16_as_ushort(l0) | ((uint32_t)__bfloat16_as_ushort(l1) << 16);
    }
    *(uint4*)(hi + e) = make_uint4(hp[0], hp[1], hp[2], hp[3]);
    *(uint4*)(lo + e) = make_uint4(lp[0], lp[1], lp[2], lp[3]);
}

// ---------------------------------------------------------------------------
// Kernel B: HMMA GEMM  k = X @ Wk^T  (K = 3*768, bf16 split)
// Epilogue writes HEAD-MAJOR layout [B, H, N, 64].
// ---------------------------------------------------------------------------
#define ROWB_ 80
#define TILEB_ (128 * ROWB_)
#define STAGEB_ (2 * TILEB_)
#define NSTG_ 3
#define GEMM_SMEM_REQ (NSTG_ * STAGEB_)  // 61440

__device__ __forceinline__ void load_tile(
    uint32_t aS, uint32_t bS, const char* Aseg, const char* Bseg,
    int mt, int nt, int kk, int tid)
{
#pragma unroll
    for (int i = 0; i < 2; i++) {
        int idx = tid + i * 256;
        int row = idx >> 2, c = idx & 3;
        cpa16(aS + row * ROWB_ + c * 16,
              Aseg + ((size_t)(mt * 128 + row) * C_ + kk + c * 8) * 2);
    }
#pragma unroll
    for (int i = 0; i < 2; i++) {
        int idx = tid + i * 256;
        int row = idx >> 2, c = idx & 3;
        cpa16(bS + row * ROWB_ + c * 16,
              Bseg + ((size_t)(nt * 128 + row) * C_ + kk + c * 8) * 2);
    }
}

__global__ void __launch_bounds__(256, 2) k_gemm_mma(
    const __nv_bfloat16* __restrict__ xh, const __nv_bfloat16* __restrict__ xl,
    const __nv_bfloat16* __restrict__ wh, const __nv_bfloat16* __restrict__ wl,
    float* __restrict__ out)
{
    extern __shared__ char dsm[];
    const uint32_t sbase = smem_u32(dsm);

    const int tid  = threadIdx.x;
    const int lane = tid & 31;
    const int warp = tid >> 5;
    const int wm   = warp >> 2;
    const int wn   = warp & 3;
    const int nt   = blockIdx.x;
    const int mt   = blockIdx.y;

    const char* Asrc[KSEG_] = {(const char*)xh, (const char*)xh, (const char*)xl};
    const char* Bsrc[KSEG_] = {(const char*)wh, (const char*)wl, (const char*)wh};

    float acc[4][4][4];
#pragma unroll
    for (int mi = 0; mi < 4; mi++)
#pragma unroll
        for (int ni = 0; ni < 4; ni++)
#pragma unroll
            for (int i = 0; i < 4; i++) acc[mi][ni][i] = 0.0f;

#pragma unroll
    for (int s = 0; s < NSTG_ - 1; s++) {
        load_tile(sbase + s * STAGEB_, sbase + s * STAGEB_ + TILEB_,
                  Asrc[0], Bsrc[0], mt, nt, s * BK_, tid);
        CP_COMMIT();
    }

    const uint32_t a_lane_off = (uint32_t)((lane & 15) * ROWB_ + (lane >> 4) * 16);
    const uint32_t b_lane_off = (uint32_t)((lane & 7) * ROWB_ + ((lane >> 3) & 1) * 16);

    for (int kc = 0; kc < NCHUNK_TOT_; kc++) {
        CP_WAIT1();
        __syncthreads();

        int pf = kc + NSTG_ - 1;
        if (pf < NCHUNK_TOT_) {
            int seg = pf / CH_PER_SEG_;
            int kk  = (pf % CH_PER_SEG_) * BK_;
            int s   = pf % NSTG_;
            load_tile(sbase + s * STAGEB_, sbase + s * STAGEB_ + TILEB_,
                      Asrc[seg], Bsrc[seg], mt, nt, kk, tid);
        }
        CP_COMMIT();

        const uint32_t aS = sbase + (kc % NSTG_) * STAGEB_;
        const uint32_t bS = aS + TILEB_;
#pragma unroll
        for (int h = 0; h < 2; h++) {
            uint32_t a[4][4], b[4][2];
#pragma unroll
            for (int mi = 0; mi < 4; mi++)
                ldsm_x4(a[mi], aS + (wm * 64 + mi * 16) * ROWB_ + h * 32 + a_lane_off);
#pragma unroll
            for (int ni = 0; ni < 4; ni++)
                ldsm_x2(b[ni], bS + (wn * 32 + ni * 8) * ROWB_ + h * 32 + b_lane_off);
#pragma unroll
            for (int mi = 0; mi < 4; mi++)
#pragma unroll
                for (int ni = 0; ni < 4; ni++)
                    mma_bf16(acc[mi][ni], a[mi], b[ni]);
        }
        __syncthreads();
    }

    // epilogue: scatter into head-major [B, H, N, 64]
#pragma unroll
    for (int mi = 0; mi < 4; mi++) {
#pragma unroll
        for (int ni = 0; ni < 4; ni++) {
            int r = mt * 128 + wm * 64 + mi * 16 + (lane >> 2);
            int c = nt * 128 + wn * 32 + ni * 8 + (lane & 3) * 2;
            int b = r >> 12, n = r & (N_ - 1);
            int hh = c >> 6, d = c & 63;
            size_t addr = (((size_t)b * H_ + hh) * N_ + n) * HD_ + d;
            float2 v0 = make_float2(acc[mi][ni][0], acc[mi][ni][1]);
            float2 v1 = make_float2(acc[mi][ni][2], acc[mi][ni][3]);
            *(float2*)&out[addr] = v0;
            *(float2*)&out[addr + 8 * HD_] = v1;   // row r+8, same b/h
        }
    }
}

// ---------------------------------------------------------------------------
// Kernel 2: small GEMM  C[M,N] = A[M,K]*B[N,K]^T (+bias)
// ---------------------------------------------------------------------------
__global__ void __launch_bounds__(256) small_gemm_nt(
    const float* __restrict__ A, const float* __restrict__ Bm,
    const float* __restrict__ bias, float* __restrict__ C,
    int M, int N, int K)
{
    __shared__ float AsT[16][17];
    __shared__ float BsT[16][65];

    const int t  = threadIdx.x;
    const int n0 = blockIdx.x * 64;
    const int m0 = blockIdx.y * 16;
    const int r0 = t >> 6;
    const int c  = t & 63;

    float acc[4] = {0.f, 0.f, 0.f, 0.f};

    for (int k0 = 0; k0 < K; k0 += 16) {
        __syncthreads();
        { int mm = t >> 4, kk = t & 15;
          AsT[kk][mm] = A[(long)(m0 + mm) * K + k0 + kk]; }
        { int nn = t >> 2, k4 = (t & 3) * 4;
          float4 v = *(const float4*)&Bm[(long)(n0 + nn) * K + k0 + k4];
          BsT[k4 + 0][nn] = v.x; BsT[k4 + 1][nn] = v.y;
          BsT[k4 + 2][nn] = v.z; BsT[k4 + 3][nn] = v.w; }
        __syncthreads();
#pragma unroll
        for (int kk = 0; kk < 16; kk++) {
            float bb = BsT[kk][c];
            acc[0] = fmaf(AsT[kk][r0 +  0], bb, acc[0]);
            acc[1] = fmaf(AsT[kk][r0 +  4], bb, acc[1]);
            acc[2] = fmaf(AsT[kk][r0 +  8], bb, acc[2]);
            acc[3] = fmaf(AsT[kk][r0 + 12], bb, acc[3]);
        }
    }
    float bv = bias ? bias[n0 + c] : 0.0f;
#pragma unroll
    for (int i = 0; i < 4; i++)
        C[(long)(m0 + r0 + 4 * i) * N + n0 + c] = acc[i] + bv;
}

// ---------------------------------------------------------------------------
// Hopfield step (split-N). k is head-major: block (split,bh) reads a fully
// contiguous 256KB region, streamed tile-by-tile (32KB linear copies).
// ---------------------------------------------------------------------------
__global__ void hop_init_q(const float* __restrict__ q0, float* __restrict__ qst)
{
    int bh = blockIdx.x, h = bh % H_;
    for (int i = threadIdx.x; i < L_ * HD_; i += 256) {
        int l = i >> 6, d = i & 63;
        qst[bh * (L_ * HD_) + i] = q0[l * C_ + h * HD_ + d];
    }
}

#define HOP_SMEM_ (2 * TN_ * HD_ * 4)   // 65536 B double buffer

__global__ void __launch_bounds__(256, 2) hop_partial(
    const float* __restrict__ qst, const float* __restrict__ kmat,
    float* __restrict__ m_part, float* __restrict__ z_part,
    float* __restrict__ acc_part)
{
    extern __shared__ __align__(16) float hsm[];  // [2][TN_*HD_]
    __shared__ float mw[NWARP_][L_];
    __shared__ float zw[NWARP_][L_];
    __shared__ float Mg[L_];

    const int t     = threadIdx.x;
    const int warp  = t >> 5;
    const int lane  = t & 31;
    const int split = blockIdx.x;
    const int bh    = blockIdx.y;
    const int l     = lane >> 1;
    const int dbase = (lane & 1) * 32;
    const float scale = 0.125f;

    // head-major: contiguous per (bh, split)
    const char* kbase = (const char*)(kmat + ((size_t)bh * N_ + (size_t)split * (N_ / NS_)) * HD_);
    const uint32_t sb = smem_u32(hsm);

    float qreg[32];
    {
        const float4* qp = (const float4*)(qst + bh * (L_ * HD_) + l * HD_ + dbase);
#pragma unroll
        for (int i = 0; i < 8; i++) {
            float4 v = qp[i];
            qreg[i*4+0] = v.x * scale; qreg[i*4+1] = v.y * scale;
            qreg[i*4+2] = v.z * scale; qreg[i*4+3] = v.w * scale;
        }
    }
    float m = -1e30f, Z = 0.0f;
    float acc[32];
#pragma unroll
    for (int i = 0; i < 32; i++) acc[i] = 0.0f;

    // prefetch tile 0 (32KB linear)
    {
#pragma unroll
        for (int i = 0; i < 8; i++) {
            int idx = t + i * 256;
            cpa16(sb + idx * 16, kbase + (size_t)idx * 16);
        }
        CP_COMMIT();
    }

    for (int tile = 0; tile < NT_SPL_; tile++) {
        if (tile + 1 < NT_SPL_) {
            uint32_t dst = sb + ((tile + 1) & 1) * (TN_ * HD_ * 4);
            const char* src = kbase + (size_t)(tile + 1) * (TN_ * HD_ * 4);
#pragma unroll
            for (int i = 0; i < 8; i++) {
                int idx = t + i * 256;
                cpa16(dst + idx * 16, src + (size_t)idx * 16);
            }
            CP_COMMIT();
            CP_WAIT1();
        } else {
            CP_WAIT0();
        }
        __syncthreads();

        const float* buf = hsm + (tile & 1) * (TN_ * HD_);

        float s[16];
#pragma unroll
        for (int jj = 0; jj < 16; jj++) {
            const float* kp = &buf[(warp * 16 + jj) * HD_ + dbase];
            float partial = 0.0f;
#pragma unroll
            for (int i = 0; i < 8; i++) {
                float4 kv = *(const float4*)&kp[i * 4];
                partial = fmaf(qreg[i*4+0], kv.x, partial);
                partial = fmaf(qreg[i*4+1], kv.y, partial);
                partial = fmaf(qreg[i*4+2], kv.z, partial);
                partial = fmaf(qreg[i*4+3], kv.w, partial);
            }
            s[jj] = partial + __shfl_xor_sync(0xffffffffu, partial, 1);
        }
        float tm = s[0];
#pragma unroll
        for (int jj = 1; jj < 16; jj++) tm = fmaxf(tm, s[jj]);
        float Mn = fmaxf(m, tm);
        float sc = __expf(m - Mn);
        Z *= sc;
#pragma unroll
        for (int i = 0; i < 32; i++) acc[i] *= sc;
#pragma unroll
        for (int jj = 0; jj < 16; jj++) {
            float p = __expf(s[jj] - Mn);
            Z += p;
            const float* kp = &buf[(warp * 16 + jj) * HD_ + dbase];
#pragma unroll
            for (int i = 0; i < 8; i++) {
                float4 kv = *(const float4*)&kp[i * 4];
                acc[i*4+0] = fmaf(p, kv.x, acc[i*4+0]);
                acc[i*4+1] = fmaf(p, kv.y, acc[i*4+1]);
                acc[i*4+2] = fmaf(p, kv.z, acc[i*4+2]);
                acc[i*4+3] = fmaf(p, kv.w, acc[i*4+3]);
            }
        }
        m = Mn;
        __syncthreads();
    }

    // block-level combine (global clamp/+exp(-M) happens in hop_combine)
    if ((lane & 1) == 0) { mw[warp][l] = m; zw[warp][l] = Z; }
    __syncthreads();
    if (t < L_) {
        float M = -1e30f;
#pragma unroll
        for (int w = 0; w < NWARP_; w++) M = fmaxf(M, mw[w][t]);
        Mg[t] = M;
        float Zt = 0.0f;
#pragma unroll
        for (int w = 0; w < NWARP_; w++)
            Zt += zw[w][t] * __expf(mw[w][t] - M);
        int o = (bh * NS_ + split) * L_ + t;
        m_part[o] = M;
        z_part[o] = Zt;
    }
    __syncthreads();
    {
        float f = __expf(m - Mg[l]);
#pragma unroll
        for (int i = 0; i < 8; i++) {
            float4 v = make_float4(acc[i*4+0]*f, acc[i*4+1]*f,
                                   acc[i*4+2]*f, acc[i*4+3]*f);
            *(float4*)&hsm[warp * (L_ * HD_) + l * HD_ + dbase + i * 4] = v;
        }
    }
    __syncthreads();
    size_t ob = (size_t)(bh * NS_ + split) * (L_ * HD_);
    for (int i = t; i < L_ * HD_; i += 256) {
        float sum = 0.0f;
#pragma unroll
        for (int w = 0; w < NWARP_; w++) sum += hsm[w * (L_ * HD_) + i];
        acc_part[ob + i] = sum;
    }
}

__global__ void hop_combine(
    const float* __restrict__ m_part, const float* __restrict__ z_part,
    const float* __restrict__ acc_part, float* __restrict__ qdst, int final_mode)
{
    __shared__ float F[NS_][L_];
    __shared__ float Zs[L_];

    const int bh = blockIdx.x;
    const int b = bh / H_, h = bh % H_;
    const int t = threadIdx.x;

    if (t < L_) {
        float mv[NS_];
        float M = 0.0f;   // softmax_1 clamp at 0
#pragma unroll
        for (int i = 0; i < NS_; i++) {
            mv[i] = m_part[(bh * NS_ + i) * L_ + t];
            M = fmaxf(M, mv[i]);
        }
        float Zt = __expf(-M);   // phantom logit 0
#pragma unroll
        for (int i = 0; i < NS_; i++) {
            float f = __expf(mv[i] - M);
            F[i][t] = f;
            Zt += z_part[(bh * NS_ + i) * L_ + t] * f;
        }
        Zs[t] = Zt;
    }
    __syncthreads();

    for (int idx = t; idx < L_ * HD_; idx += 256) {
        int l = idx >> 6, d = idx & 63;
        float sum = 0.0f;
#pragma unroll
        for (int i = 0; i < NS_; i++)
            sum += acc_part[(size_t)(bh * NS_ + i) * (L_ * HD_) + idx] * F[i][l];
        sum /= Zs[l];
        if (final_mode)
            qdst[((size_t)b * L_ + l) * C_ + h * HD_ + d] = sum;
        else
            qdst[bh * (L_ * HD_) + idx] = sum;
    }
}

// ---------------------------------------------------------------------------
// Launch
// ---------------------------------------------------------------------------
extern "C" void kernel_launch(void* const* d_in, const int* in_sizes, int n_in,
                              void* d_out, int out_size)
{
    const float* x     = (const float*)d_in[0];
    const float* query = (const float*)d_in[1];
    const float* Wq    = (const float*)d_in[2];
    const float* Wk    = (const float*)d_in[3];
    const float* Wv    = (const float*)d_in[4];
    const float* Wproj = (const float*)d_in[5];
    const float* bproj = (const float*)d_in[6];
    float* out = (float*)d_out;

    float *k_scr, *q0_scr, *qf_scr, *tmp_scr, *q_state, *m_part, *z_part, *acc_part;
    __nv_bfloat16 *xh, *xl, *wh, *wl;
    cudaGetSymbolAddress((void**)&k_scr,  g_k_scr);
    cudaGetSymbolAddress((void**)&q0_scr, g_q0_scr);
    cudaGetSymbolAddress((void**)&qf_scr, g_qf_scr);
    cudaGetSymbolAddress((void**)&tmp_scr, g_tmp_scr);
    cudaGetSymbolAddress((void**)&q_state, g_q_state);
    cudaGetSymbolAddress((void**)&m_part, g_m_part);
    cudaGetSymbolAddress((void**)&z_part, g_z_part);
    cudaGetSymbolAddress((void**)&acc_part, g_acc_part);
    cudaGetSymbolAddress((void**)&xh, g_xh);
    cudaGetSymbolAddress((void**)&xl, g_xl);
    cudaGetSymbolAddress((void**)&wh, g_wh);
    cudaGetSymbolAddress((void**)&wl, g_wl);

    static bool attr_set = false;
    if (!attr_set) {
        cudaFuncSetAttribute(k_gemm_mma, cudaFuncAttributeMaxDynamicSharedMemorySize,
                             GEMM_SMEM_REQ);
        cudaFuncSetAttribute(hop_partial, cudaFuncAttributeMaxDynamicSharedMemorySize,
                             HOP_SMEM_);
        attr_set = true;
    }

    // split/convert x and Wk into row-major bf16 hi/lo
    {
        int nch_x = (MROWS_ * C_) / 8;
        convert_split_kernel<<<(nch_x + 255) / 256, 256>>>(x, xh, xl, nch_x);
        int nch_w = (C_ * C_) / 8;
        convert_split_kernel<<<(nch_w + 255) / 256, 256>>>(Wk, wh, wl, nch_w);
    }
    // q0 = query @ Wq^T
    small_gemm_nt<<<dim3(C_ / 64, 1), 256>>>(query, Wq, nullptr, q0_scr, L_, C_, C_);
    // k = x @ Wk^T via HMMA, head-major output
    k_gemm_mma<<<dim3(C_ / 128, MROWS_ / 128), 256, GEMM_SMEM_REQ>>>(xh, xl, wh, wl, k_scr);
    // 3-step Hopfield attention, split-N over contiguous per-head k
    hop_init_q<<<BH_, 256>>>(q0_scr, q_state);
    for (int s = 0; s < STEPS_; s++) {
        hop_partial<<<dim3(NS_, BH_), 256, HOP_SMEM_>>>(
            q_state, k_scr, m_part, z_part, acc_part);
        hop_combine<<<BH_, 256>>>(m_part, z_part, acc_part,
                                  (s == STEPS_ - 1) ? qf_scr : q_state,
                                  (s == STEPS_ - 1) ? 1 : 0);
    }
    // out projections
    small_gemm_nt<<<dim3(C_ / 64, (B_ * L_) / 16), 256>>>(
        qf_scr, Wv, nullptr, tmp_scr, B_ * L_, C_, C_);
    small_gemm_nt<<<dim3(C_ / 64, (B_ * L_) / 16), 256>>>(
        tmp_scr, Wproj, bproj, out, B_ * L_, C_, C_);
}

// round 6
// speedup vs baseline: 4.3440x; 4.2686x over previous
#include <cuda_runtime.h>
#include <cuda_bf16.h>
#include <cstdint>

// ---------------------------------------------------------------------------
// Shapes (fixed by the problem)
// ---------------------------------------------------------------------------
#define B_  16
#define N_  4096
#define C_  768
#define L_  16
#define H_  12
#define HD_ 64
#define STEPS_ 3
#define BH_ (B_ * H_)               // 192

#define MROWS_ (B_ * N_)            // 65536
#define KSEG_  3                    // hi*hi, hi*lo, lo*hi
#define BK_    32
#define CH_PER_SEG_ (C_ / BK_)      // 24
#define NCHUNK_TOT_ (KSEG_ * CH_PER_SEG_)  // 72

// Hopfield split
#define TN_ 128
#define NWARP_ 8
#define NS_ 4
#define NT_SPL_ (N_ / NS_ / TN_)    // 8 tiles per split

// ---------------------------------------------------------------------------
// Scratch (__device__ globals)
// k stored as bf16 hi/lo, HEAD-MAJOR [B, H, N, 64]
// ---------------------------------------------------------------------------
__device__ __align__(16) __nv_bfloat16 g_kh[(size_t)BH_ * N_ * HD_];
__device__ __align__(16) __nv_bfloat16 g_kl[(size_t)BH_ * N_ * HD_];
__device__ __align__(16) __nv_bfloat16 g_xh[(size_t)MROWS_ * C_];
__device__ __align__(16) __nv_bfloat16 g_xl[(size_t)MROWS_ * C_];
__device__ __align__(16) __nv_bfloat16 g_wh[(size_t)C_ * C_];
__device__ __align__(16) __nv_bfloat16 g_wl[(size_t)C_ * C_];
__device__ float g_q0_scr[L_ * C_];
__device__ float g_qf_scr[B_ * L_ * C_];
__device__ float g_tmp_scr[B_ * L_ * C_];
__device__ __align__(16) float g_q_state[BH_ * L_ * HD_];
__device__ float g_m_part[BH_ * NS_ * L_];
__device__ float g_z_part[BH_ * NS_ * L_];
__device__ __align__(16) float g_acc_part[(size_t)BH_ * NS_ * L_ * HD_];

// ---------------------------------------------------------------------------
// helpers
// ---------------------------------------------------------------------------
__device__ __forceinline__ uint32_t smem_u32(const void* p) {
    uint32_t a;
    asm("{ .reg .u64 t; cvta.to.shared.u64 t, %1; cvt.u32.u64 %0, t; }" : "=r"(a) : "l"(p));
    return a;
}
__device__ __forceinline__ void cpa16(uint32_t dst, const void* src) {
    asm volatile("cp.async.cg.shared.global [%0], [%1], 16;" :: "r"(dst), "l"(src));
}
#define CP_COMMIT() asm volatile("cp.async.commit_group;" ::: "memory")
#define CP_WAIT1()  asm volatile("cp.async.wait_group 1;" ::: "memory")
#define CP_WAIT0()  asm volatile("cp.async.wait_group 0;" ::: "memory")

__device__ __forceinline__ void ldsm_x4(uint32_t* r, uint32_t addr) {
    asm volatile("ldmatrix.sync.aligned.m8n8.x4.shared.b16 {%0,%1,%2,%3}, [%4];"
                 : "=r"(r[0]), "=r"(r[1]), "=r"(r[2]), "=r"(r[3]) : "r"(addr));
}
__device__ __forceinline__ void ldsm_x2(uint32_t* r, uint32_t addr) {
    asm volatile("ldmatrix.sync.aligned.m8n8.x2.shared.b16 {%0,%1}, [%2];"
                 : "=r"(r[0]), "=r"(r[1]) : "r"(addr));
}
__device__ __forceinline__ void ldsm_x4t(uint32_t* r, uint32_t addr) {
    asm volatile("ldmatrix.sync.aligned.m8n8.x4.trans.shared.b16 {%0,%1,%2,%3}, [%4];"
                 : "=r"(r[0]), "=r"(r[1]), "=r"(r[2]), "=r"(r[3]) : "r"(addr));
}
__device__ __forceinline__ void mma_bf16(float* d, const uint32_t* a, const uint32_t* b) {
    asm volatile(
        "mma.sync.aligned.m16n8k16.row.col.f32.bf16.bf16.f32 "
        "{%0,%1,%2,%3}, {%4,%5,%6,%7}, {%8,%9}, {%0,%1,%2,%3};"
        : "+f"(d[0]), "+f"(d[1]), "+f"(d[2]), "+f"(d[3])
        : "r"(a[0]), "r"(a[1]), "r"(a[2]), "r"(a[3]), "r"(b[0]), "r"(b[1]));
}
__device__ __forceinline__ void split2(float a, float b, uint32_t* hi, uint32_t* lo) {
    __nv_bfloat16 ha = __float2bfloat16(a), hb = __float2bfloat16(b);
    __nv_bfloat16 la = __float2bfloat16(a - __bfloat162float(ha));
    __nv_bfloat16 lb = __float2bfloat16(b - __bfloat162float(hb));
    *hi = (uint32_t)__bfloat16_as_ushort(ha) | ((uint32_t)__bfloat16_as_ushort(hb) << 16);
    *lo = (uint32_t)__bfloat16_as_ushort(la) | ((uint32_t)__bfloat16_as_ushort(lb) << 16);
}

// ---------------------------------------------------------------------------
// Kernel A: split fp32 -> (hi, lo) bf16, plain row-major
// ---------------------------------------------------------------------------
__global__ void __launch_bounds__(256) convert_split_kernel(
    const float* __restrict__ src, __nv_bfloat16* __restrict__ hi,
    __nv_bfloat16* __restrict__ lo, int nchunks)
{
    int idx = blockIdx.x * 256 + threadIdx.x;
    if (idx >= nchunks) return;
    size_t e = (size_t)idx * 8;

    const float4* p = (const float4*)(src + e);
    float4 a = p[0], b = p[1];
    float v[8] = {a.x, a.y, a.z, a.w, b.x, b.y, b.z, b.w};

    uint32_t hp[4], lp[4];
#pragma unroll
    for (int i = 0; i < 4; i++) split2(v[2*i], v[2*i+1], &hp[i], &lp[i]);
    *(uint4*)(hi + e) = make_uint4(hp[0], hp[1], hp[2], hp[3]);
    *(uint4*)(lo + e) = make_uint4(lp[0], lp[1], lp[2], lp[3]);
}

// ---------------------------------------------------------------------------
// Kernel B: HMMA GEMM  k = X @ Wk^T  (K = 3*768, bf16 split)
// Epilogue emits kh/kl bf16 HEAD-MAJOR [B, H, N, 64].
// ---------------------------------------------------------------------------
#define ROWB_ 80
#define TILEB_ (128 * ROWB_)
#define STAGEB_ (2 * TILEB_)
#define NSTG_ 3
#define GEMM_SMEM_REQ (NSTG_ * STAGEB_)  // 61440

__device__ __forceinline__ void load_tile(
    uint32_t aS, uint32_t bS, const char* Aseg, const char* Bseg,
    int mt, int nt, int kk, int tid)
{
#pragma unroll
    for (int i = 0; i < 2; i++) {
        int idx = tid + i * 256;
        int row = idx >> 2, c = idx & 3;
        cpa16(aS + row * ROWB_ + c * 16,
              Aseg + ((size_t)(mt * 128 + row) * C_ + kk + c * 8) * 2);
    }
#pragma unroll
    for (int i = 0; i < 2; i++) {
        int idx = tid + i * 256;
        int row = idx >> 2, c = idx & 3;
        cpa16(bS + row * ROWB_ + c * 16,
              Bseg + ((size_t)(nt * 128 + row) * C_ + kk + c * 8) * 2);
    }
}

__global__ void __launch_bounds__(256, 2) k_gemm_mma(
    const __nv_bfloat16* __restrict__ xh, const __nv_bfloat16* __restrict__ xl,
    const __nv_bfloat16* __restrict__ wh, const __nv_bfloat16* __restrict__ wl,
    __nv_bfloat16* __restrict__ khg, __nv_bfloat16* __restrict__ klg)
{
    extern __shared__ char dsm[];
    const uint32_t sbase = smem_u32(dsm);

    const int tid  = threadIdx.x;
    const int lane = tid & 31;
    const int warp = tid >> 5;
    const int wm   = warp >> 2;
    const int wn   = warp & 3;
    const int nt   = blockIdx.x;
    const int mt   = blockIdx.y;

    const char* Asrc[KSEG_] = {(const char*)xh, (const char*)xh, (const char*)xl};
    const char* Bsrc[KSEG_] = {(const char*)wh, (const char*)wl, (const char*)wh};

    float acc[4][4][4];
#pragma unroll
    for (int mi = 0; mi < 4; mi++)
#pragma unroll
        for (int ni = 0; ni < 4; ni++)
#pragma unroll
            for (int i = 0; i < 4; i++) acc[mi][ni][i] = 0.0f;

#pragma unroll
    for (int s = 0; s < NSTG_ - 1; s++) {
        load_tile(sbase + s * STAGEB_, sbase + s * STAGEB_ + TILEB_,
                  Asrc[0], Bsrc[0], mt, nt, s * BK_, tid);
        CP_COMMIT();
    }

    const uint32_t a_lane_off = (uint32_t)((lane & 15) * ROWB_ + (lane >> 4) * 16);
    const uint32_t b_lane_off = (uint32_t)((lane & 7) * ROWB_ + ((lane >> 3) & 1) * 16);

    for (int kc = 0; kc < NCHUNK_TOT_; kc++) {
        CP_WAIT1();
        __syncthreads();

        int pf = kc + NSTG_ - 1;
        if (pf < NCHUNK_TOT_) {
            int seg = pf / CH_PER_SEG_;
            int kk  = (pf % CH_PER_SEG_) * BK_;
            int s   = pf % NSTG_;
            load_tile(sbase + s * STAGEB_, sbase + s * STAGEB_ + TILEB_,
                      Asrc[seg], Bsrc[seg], mt, nt, kk, tid);
        }
        CP_COMMIT();

        const uint32_t aS = sbase + (kc % NSTG_) * STAGEB_;
        const uint32_t bS = aS + TILEB_;
#pragma unroll
        for (int h = 0; h < 2; h++) {
            uint32_t a[4][4], b[4][2];
#pragma unroll
            for (int mi = 0; mi < 4; mi++)
                ldsm_x4(a[mi], aS + (wm * 64 + mi * 16) * ROWB_ + h * 32 + a_lane_off);
#pragma unroll
            for (int ni = 0; ni < 4; ni++)
                ldsm_x2(b[ni], bS + (wn * 32 + ni * 8) * ROWB_ + h * 32 + b_lane_off);
#pragma unroll
            for (int mi = 0; mi < 4; mi++)
#pragma unroll
                for (int ni = 0; ni < 4; ni++)
                    mma_bf16(acc[mi][ni], a[mi], b[ni]);
        }
        __syncthreads();
    }

    // epilogue: split to bf16 hi/lo, scatter head-major [B, H, N, 64]
#pragma unroll
    for (int mi = 0; mi < 4; mi++) {
#pragma unroll
        for (int ni = 0; ni < 4; ni++) {
            int r = mt * 128 + wm * 64 + mi * 16 + (lane >> 2);
            int c = nt * 128 + wn * 32 + ni * 8 + (lane & 3) * 2;
            int b = r >> 12, n = r & (N_ - 1);
            int hh = c >> 6, d = c & 63;
            size_t addr = (((size_t)b * H_ + hh) * N_ + n) * HD_ + d;
            uint32_t h01, l01, h23, l23;
            split2(acc[mi][ni][0], acc[mi][ni][1], &h01, &l01);
            split2(acc[mi][ni][2], acc[mi][ni][3], &h23, &l23);
            *(uint32_t*)&khg[addr] = h01;
            *(uint32_t*)&klg[addr] = l01;
            *(uint32_t*)&khg[addr + 8 * HD_] = h23;   // row r+8
            *(uint32_t*)&klg[addr + 8 * HD_] = l23;
        }
    }
}

// ---------------------------------------------------------------------------
// Kernel 2: small GEMM  C[M,N] = A[M,K]*B[N,K]^T (+bias)
// ---------------------------------------------------------------------------
__global__ void __launch_bounds__(256) small_gemm_nt(
    const float* __restrict__ A, const float* __restrict__ Bm,
    const float* __restrict__ bias, float* __restrict__ C,
    int M, int N, int K)
{
    __shared__ float AsT[16][17];
    __shared__ float BsT[16][65];

    const int t  = threadIdx.x;
    const int n0 = blockIdx.x * 64;
    const int m0 = blockIdx.y * 16;
    const int r0 = t >> 6;
    const int c  = t & 63;

    float acc[4] = {0.f, 0.f, 0.f, 0.f};

    for (int k0 = 0; k0 < K; k0 += 16) {
        __syncthreads();
        { int mm = t >> 4, kk = t & 15;
          AsT[kk][mm] = A[(long)(m0 + mm) * K + k0 + kk]; }
        { int nn = t >> 2, k4 = (t & 3) * 4;
          float4 v = *(const float4*)&Bm[(long)(n0 + nn) * K + k0 + k4];
          BsT[k4 + 0][nn] = v.x; BsT[k4 + 1][nn] = v.y;
          BsT[k4 + 2][nn] = v.z; BsT[k4 + 3][nn] = v.w; }
        __syncthreads();
#pragma unroll
        for (int kk = 0; kk < 16; kk++) {
            float bb = BsT[kk][c];
            acc[0] = fmaf(AsT[kk][r0 +  0], bb, acc[0]);
            acc[1] = fmaf(AsT[kk][r0 +  4], bb, acc[1]);
            acc[2] = fmaf(AsT[kk][r0 +  8], bb, acc[2]);
            acc[3] = fmaf(AsT[kk][r0 + 12], bb, acc[3]);
        }
    }
    float bv = bias ? bias[n0 + c] : 0.0f;
#pragma unroll
    for (int i = 0; i < 4; i++)
        C[(long)(m0 + r0 + 4 * i) * N + n0 + c] = acc[i] + bv;
}

// ---------------------------------------------------------------------------
// Hopfield step via HMMA (flash-attn v2 structure), split-N.
// Per warp: 16 keys of each 128-key tile. Scores S = qh·kh + qh·kl + ql·kh.
// P = exp(S - m), split to ph/pl; O += ph·kh + ph·kl + pl·kh.
// ---------------------------------------------------------------------------
__global__ void hop_init_q(const float* __restrict__ q0, float* __restrict__ qst)
{
    int bh = blockIdx.x, h = bh % H_;
    for (int i = threadIdx.x; i < L_ * HD_; i += 256) {
        int l = i >> 6, d = i & 63;
        qst[bh * (L_ * HD_) + i] = q0[l * C_ + h * HD_ + d];
    }
}

#define KROW_ 144                       // 64 bf16 = 128B + 16B pad
#define KTILE_PAD_ (128 * KROW_)        // 18432
#define HOP_SMEM_ (4 * KTILE_PAD_ + 2 * L_ * KROW_)   // 78336

__global__ void __launch_bounds__(256, 2) hop_partial(
    const float* __restrict__ qst,
    const __nv_bfloat16* __restrict__ khg, const __nv_bfloat16* __restrict__ klg,
    float* __restrict__ m_part, float* __restrict__ z_part,
    float* __restrict__ acc_part)
{
    extern __shared__ __align__(16) char hsm8[];
    __shared__ float mw[NWARP_][L_];
    __shared__ float zw[NWARP_][L_];
    __shared__ float Mg[L_];

    const int t     = threadIdx.x;
    const int warp  = t >> 5;
    const int lane  = t & 31;
    const int split = blockIdx.x;
    const int bh    = blockIdx.y;
    const uint32_t sb  = smem_u32(hsm8);
    const uint32_t KH0 = sb;
    const uint32_t KL0 = sb + 2 * KTILE_PAD_;
    const uint32_t QHo = sb + 4 * KTILE_PAD_;
    const uint32_t QLo = QHo + L_ * KROW_;

    const char* ksrc_h = (const char*)(khg + ((size_t)bh * N_ + split * (N_ / NS_)) * HD_);
    const char* ksrc_l = (const char*)(klg + ((size_t)bh * N_ + split * (N_ / NS_)) * HD_);

    // prefetch tile 0 (kh+kl, 16KB each, into padded rows)
#pragma unroll
    for (int i = 0; i < 4; i++) {
        int idx = t + i * 256;                 // 0..1023
        int row = idx >> 3, c = idx & 7;
        cpa16(KH0 + row * KROW_ + c * 16, ksrc_h + (size_t)idx * 16);
        cpa16(KL0 + row * KROW_ + c * 16, ksrc_l + (size_t)idx * 16);
    }
    CP_COMMIT();

    // q: scale, split, park in padded smem (ldmatrix-ready)
    {
        float4 v = ((const float4*)(qst + bh * (L_ * HD_)))[t];
        int e = t * 4, r = e >> 6, d = e & 63;
        uint32_t h01, l01, h23, l23;
        split2(v.x * 0.125f, v.y * 0.125f, &h01, &l01);
        split2(v.z * 0.125f, v.w * 0.125f, &h23, &l23);
        char* qh = hsm8 + 4 * KTILE_PAD_ + r * KROW_ + d * 2;
        char* ql = qh + L_ * KROW_;
        *(uint32_t*)qh = h01; *(uint32_t*)(qh + 4) = h23;
        *(uint32_t*)ql = l01; *(uint32_t*)(ql + 4) = l23;
    }

    float S[2][4], O[8][4];
#pragma unroll
    for (int i = 0; i < 8; i++)
#pragma unroll
        for (int j = 0; j < 4; j++) O[i][j] = 0.0f;
    float m0 = -1e30f, m1 = -1e30f, Z0 = 0.0f, Z1 = 0.0f;

    // ldmatrix lane offsets
    const uint32_t qa_off = (uint32_t)((lane & 15) * KROW_ + (lane >> 4) * 16);
    const uint32_t kb_off = (uint32_t)((warp * 16 + ((lane >> 4) & 1) * 8 + (lane & 7)) * KROW_
                                       + ((lane >> 3) & 1) * 16);
    const uint32_t v_off  = (uint32_t)((warp * 16 + (lane & 15)) * KROW_ + (lane >> 4) * 16);

    for (int tile = 0; tile < NT_SPL_; tile++) {
        if (tile + 1 < NT_SPL_) {
            uint32_t khd = KH0 + ((tile + 1) & 1) * KTILE_PAD_;
            uint32_t kld = KL0 + ((tile + 1) & 1) * KTILE_PAD_;
            const char* sh = ksrc_h + (size_t)(tile + 1) * (TN_ * HD_ * 2);
            const char* sl = ksrc_l + (size_t)(tile + 1) * (TN_ * HD_ * 2);
#pragma unroll
            for (int i = 0; i < 4; i++) {
                int idx = t + i * 256;
                int row = idx >> 3, c = idx & 7;
                cpa16(khd + row * KROW_ + c * 16, sh + (size_t)idx * 16);
                cpa16(kld + row * KROW_ + c * 16, sl + (size_t)idx * 16);
            }
            CP_COMMIT();
            CP_WAIT1();
        } else {
            CP_WAIT0();
        }
        __syncthreads();

        const uint32_t khb = KH0 + (tile & 1) * KTILE_PAD_;
        const uint32_t klb = KL0 + (tile & 1) * KTILE_PAD_;

        // ---- scores: S[2 ntiles][4], 3-term split ----
#pragma unroll
        for (int nt = 0; nt < 2; nt++)
#pragma unroll
            for (int i = 0; i < 4; i++) S[nt][i] = 0.0f;
#pragma unroll
        for (int kc = 0; kc < 4; kc++) {
            uint32_t qh4[4], ql4[4], bh4[4], bl4[4];
            ldsm_x4(qh4, QHo + qa_off + kc * 32);
            ldsm_x4(ql4, QLo + qa_off + kc * 32);
            ldsm_x4(bh4, khb + kb_off + kc * 32);
            ldsm_x4(bl4, klb + kb_off + kc * 32);
            mma_bf16(S[0], qh4, bh4);
            mma_bf16(S[1], qh4, bh4 + 2);
            mma_bf16(S[0], qh4, bl4);
            mma_bf16(S[1], qh4, bl4 + 2);
            mma_bf16(S[0], ql4, bh4);
            mma_bf16(S[1], ql4, bh4 + 2);
        }

        // ---- online softmax (rows r = lane>>2 and r+8) ----
        float mx0 = fmaxf(fmaxf(S[0][0], S[0][1]), fmaxf(S[1][0], S[1][1]));
        float mx1 = fmaxf(fmaxf(S[0][2], S[0][3]), fmaxf(S[1][2], S[1][3]));
        mx0 = fmaxf(mx0, __shfl_xor_sync(0xffffffffu, mx0, 1));
        mx0 = fmaxf(mx0, __shfl_xor_sync(0xffffffffu, mx0, 2));
        mx1 = fmaxf(mx1, __shfl_xor_sync(0xffffffffu, mx1, 1));
        mx1 = fmaxf(mx1, __shfl_xor_sync(0xffffffffu, mx1, 2));
        float mn0 = fmaxf(m0, mx0), mn1 = fmaxf(m1, mx1);
        float f0 = __expf(m0 - mn0), f1 = __expf(m1 - mn1);
        Z0 *= f0; Z1 *= f1;
#pragma unroll
        for (int nt = 0; nt < 8; nt++) {
            O[nt][0] *= f0; O[nt][1] *= f0;
            O[nt][2] *= f1; O[nt][3] *= f1;
        }
        float P00 = __expf(S[0][0] - mn0), P01 = __expf(S[0][1] - mn0);
        float P02 = __expf(S[0][2] - mn1), P03 = __expf(S[0][3] - mn1);
        float P10 = __expf(S[1][0] - mn0), P11 = __expf(S[1][1] - mn0);
        float P12 = __expf(S[1][2] - mn1), P13 = __expf(S[1][3] - mn1);
        Z0 += P00 + P01 + P10 + P11;
        Z1 += P02 + P03 + P12 + P13;
        // P -> A fragments (k = this warp's 16 keys), hi/lo split
        uint32_t ph[4], pl[4];
        split2(P00, P01, &ph[0], &pl[0]);   // (r,   k0..1)
        split2(P02, P03, &ph[1], &pl[1]);   // (r+8, k0..1)
        split2(P10, P11, &ph[2], &pl[2]);   // (r,   k8..9)
        split2(P12, P13, &ph[3], &pl[3]);   // (r+8, k8..9)
        m0 = mn0; m1 = mn1;

        // ---- AV: O[8 hd-tiles][4] += P x V (ldmatrix.trans on k tile) ----
#pragma unroll
        for (int hp = 0; hp < 4; hp++) {
            uint32_t vh4[4], vl4[4];
            ldsm_x4t(vh4, khb + v_off + hp * 32);
            ldsm_x4t(vl4, klb + v_off + hp * 32);
            mma_bf16(O[2*hp],     ph, vh4);
            mma_bf16(O[2*hp],     ph, vl4);
            mma_bf16(O[2*hp],     pl, vh4);
            mma_bf16(O[2*hp + 1], ph, vh4 + 2);
            mma_bf16(O[2*hp + 1], ph, vl4 + 2);
            mma_bf16(O[2*hp + 1], pl, vh4 + 2);
        }
        __syncthreads();
    }

    // ---- block combine (same contract as before) ----
    Z0 += __shfl_xor_sync(0xffffffffu, Z0, 1);
    Z0 += __shfl_xor_sync(0xffffffffu, Z0, 2);
    Z1 += __shfl_xor_sync(0xffffffffu, Z1, 1);
    Z1 += __shfl_xor_sync(0xffffffffu, Z1, 2);
    const int r = lane >> 2;
    if ((lane & 3) == 0) {
        mw[warp][r]     = m0;  mw[warp][r + 8] = m1;
        zw[warp][r]     = Z0;  zw[warp][r + 8] = Z1;
    }
    __syncthreads();
    if (t < L_) {
        float M = -1e30f;
#pragma unroll
        for (int w = 0; w < NWARP_; w++) M = fmaxf(M, mw[w][t]);
        Mg[t] = M;
        float Zt = 0.0f;
#pragma unroll
        for (int w = 0; w < NWARP_; w++)
            Zt += zw[w][t] * __expf(mw[w][t] - M);
        int o = (bh * NS_ + split) * L_ + t;
        m_part[o] = M;
        z_part[o] = Zt;
    }
    __syncthreads();
    {
        float g0 = __expf(m0 - Mg[r]);
        float g1 = __expf(m1 - Mg[r + 8]);
        float* cb = (float*)hsm8 + warp * (L_ * HD_);
        int cbase = (lane & 3) * 2;
#pragma unroll
        for (int nt = 0; nt < 8; nt++) {
            int col = nt * 8 + cbase;
            *(float2*)&cb[r * HD_ + col]       = make_float2(O[nt][0] * g0, O[nt][1] * g0);
            *(float2*)&cb[(r + 8) * HD_ + col] = make_float2(O[nt][2] * g1, O[nt][3] * g1);
        }
    }
    __syncthreads();
    {
        const float* call = (const float*)hsm8;
        size_t ob = (size_t)(bh * NS_ + split) * (L_ * HD_);
        for (int i = t; i < L_ * HD_; i += 256) {
            float s = 0.0f;
#pragma unroll
            for (int w = 0; w < NWARP_; w++) s += call[w * (L_ * HD_) + i];
            acc_part[ob + i] = s;
        }
    }
}

__global__ void hop_combine(
    const float* __restrict__ m_part, const float* __restrict__ z_part,
    const float* __restrict__ acc_part, float* __restrict__ qdst, int final_mode)
{
    __shared__ float F[NS_][L_];
    __shared__ float Zs[L_];

    const int bh = blockIdx.x;
    const int b = bh / H_, h = bh % H_;
    const int t = threadIdx.x;

    if (t < L_) {
        float mv[NS_];
        float M = 0.0f;   // softmax_1 clamp at 0
#pragma unroll
        for (int i = 0; i < NS_; i++) {
            mv[i] = m_part[(bh * NS_ + i) * L_ + t];
            M = fmaxf(M, mv[i]);
        }
        float Zt = __expf(-M);   // phantom logit 0
#pragma unroll
        for (int i = 0; i < NS_; i++) {
            float f = __expf(mv[i] - M);
            F[i][t] = f;
            Zt += z_part[(bh * NS_ + i) * L_ + t] * f;
        }
        Zs[t] = Zt;
    }
    __syncthreads();

    for (int idx = t; idx < L_ * HD_; idx += 256) {
        int l = idx >> 6, d = idx & 63;
        float sum = 0.0f;
#pragma unroll
        for (int i = 0; i < NS_; i++)
            sum += acc_part[(size_t)(bh * NS_ + i) * (L_ * HD_) + idx] * F[i][l];
        sum /= Zs[l];
        if (final_mode)
            qdst[((size_t)b * L_ + l) * C_ + h * HD_ + d] = sum;
        else
            qdst[bh * (L_ * HD_) + idx] = sum;
    }
}

// ---------------------------------------------------------------------------
// Launch
// ---------------------------------------------------------------------------
extern "C" void kernel_launch(void* const* d_in, const int* in_sizes, int n_in,
                              void* d_out, int out_size)
{
    const float* x     = (const float*)d_in[0];
    const float* query = (const float*)d_in[1];
    const float* Wq    = (const float*)d_in[2];
    const float* Wk    = (const float*)d_in[3];
    const float* Wv    = (const float*)d_in[4];
    const float* Wproj = (const float*)d_in[5];
    const float* bproj = (const float*)d_in[6];
    float* out = (float*)d_out;

    float *q0_scr, *qf_scr, *tmp_scr, *q_state, *m_part, *z_part, *acc_part;
    __nv_bfloat16 *xh, *xl, *wh, *wl, *khg, *klg;
    cudaGetSymbolAddress((void**)&q0_scr, g_q0_scr);
    cudaGetSymbolAddress((void**)&qf_scr, g_qf_scr);
    cudaGetSymbolAddress((void**)&tmp_scr, g_tmp_scr);
    cudaGetSymbolAddress((void**)&q_state, g_q_state);
    cudaGetSymbolAddress((void**)&m_part, g_m_part);
    cudaGetSymbolAddress((void**)&z_part, g_z_part);
    cudaGetSymbolAddress((void**)&acc_part, g_acc_part);
    cudaGetSymbolAddress((void**)&xh, g_xh);
    cudaGetSymbolAddress((void**)&xl, g_xl);
    cudaGetSymbolAddress((void**)&wh, g_wh);
    cudaGetSymbolAddress((void**)&wl, g_wl);
    cudaGetSymbolAddress((void**)&khg, g_kh);
    cudaGetSymbolAddress((void**)&klg, g_kl);

    static bool attr_set = false;
    if (!attr_set) {
        cudaFuncSetAttribute(k_gemm_mma, cudaFuncAttributeMaxDynamicSharedMemorySize,
                             GEMM_SMEM_REQ);
        cudaFuncSetAttribute(hop_partial, cudaFuncAttributeMaxDynamicSharedMemorySize,
                             HOP_SMEM_);
        attr_set = true;
    }

    // split/convert x and Wk into row-major bf16 hi/lo
    {
        int nch_x = (MROWS_ * C_) / 8;
        convert_split_kernel<<<(nch_x + 255) / 256, 256>>>(x, xh, xl, nch_x);
        int nch_w = (C_ * C_) / 8;
        convert_split_kernel<<<(nch_w + 255) / 256, 256>>>(Wk, wh, wl, nch_w);
    }
    // q0 = query @ Wq^T
    small_gemm_nt<<<dim3(C_ / 64, 1), 256>>>(query, Wq, nullptr, q0_scr, L_, C_, C_);
    // k = x @ Wk^T via HMMA -> kh/kl bf16 head-major
    k_gemm_mma<<<dim3(C_ / 128, MROWS_ / 128), 256, GEMM_SMEM_REQ>>>(xh, xl, wh, wl, khg, klg);
    // 3-step Hopfield attention (HMMA flash)
    hop_init_q<<<BH_, 256>>>(q0_scr, q_state);
    for (int s = 0; s < STEPS_; s++) {
        hop_partial<<<dim3(NS_, BH_), 256, HOP_SMEM_>>>(
            q_state, khg, klg, m_part, z_part, acc_part);
        hop_combine<<<BH_, 256>>>(m_part, z_part, acc_part,
                                  (s == STEPS_ - 1) ? qf_scr : q_state,
                                  (s == STEPS_ - 1) ? 1 : 0);
    }
    // out projections
    small_gemm_nt<<<dim3(C_ / 64, (B_ * L_) / 16), 256>>>(
        qf_scr, Wv, nullptr, tmp_scr, B_ * L_, C_, C_);
    small_gemm_nt<<<dim3(C_ / 64, (B_ * L_) / 16), 256>>>(
        tmp_scr, Wproj, bproj, out, B_ * L_, C_, C_);
}

// round 7
// speedup vs baseline: 5.3473x; 1.2310x over previous
#include <cuda_runtime.h>
#include <cuda_bf16.h>
#include <cstdint>

// ---------------------------------------------------------------------------
// Shapes (fixed by the problem)
// ---------------------------------------------------------------------------
#define B_  16
#define N_  4096
#define C_  768
#define L_  16
#define H_  12
#define HD_ 64
#define STEPS_ 3
#define BH_ (B_ * H_)               // 192

#define MROWS_ (B_ * N_)            // 65536
#define KSEG_  3                    // hi*hi, hi*lo, lo*hi
#define BK_    64                   // k per pipeline chunk
#define CH_PER_SEG_ (C_ / BK_)      // 12
#define NCHUNK_TOT_ (KSEG_ * CH_PER_SEG_)  // 36

// Hopfield split
#define TN_ 128
#define NWARP_ 8
#define NS_ 4
#define NT_SPL_ (N_ / NS_ / TN_)    // 8 tiles per split

// ---------------------------------------------------------------------------
// Scratch (__device__ globals)
// k stored as bf16 hi/lo, HEAD-MAJOR [B, H, N, 64]
// ---------------------------------------------------------------------------
__device__ __align__(16) __nv_bfloat16 g_kh[(size_t)BH_ * N_ * HD_];
__device__ __align__(16) __nv_bfloat16 g_kl[(size_t)BH_ * N_ * HD_];
__device__ __align__(16) __nv_bfloat16 g_xh[(size_t)MROWS_ * C_];
__device__ __align__(16) __nv_bfloat16 g_xl[(size_t)MROWS_ * C_];
__device__ __align__(16) __nv_bfloat16 g_wh[(size_t)C_ * C_];
__device__ __align__(16) __nv_bfloat16 g_wl[(size_t)C_ * C_];
__device__ float g_q0_scr[L_ * C_];
__device__ float g_qf_scr[B_ * L_ * C_];
__device__ float g_tmp_scr[B_ * L_ * C_];
__device__ __align__(16) float g_q_state[BH_ * L_ * HD_];
__device__ float g_m_part[BH_ * NS_ * L_];
__device__ float g_z_part[BH_ * NS_ * L_];
__device__ __align__(16) float g_acc_part[(size_t)BH_ * NS_ * L_ * HD_];

// ---------------------------------------------------------------------------
// helpers
// ---------------------------------------------------------------------------
__device__ __forceinline__ uint32_t smem_u32(const void* p) {
    uint32_t a;
    asm("{ .reg .u64 t; cvta.to.shared.u64 t, %1; cvt.u32.u64 %0, t; }" : "=r"(a) : "l"(p));
    return a;
}
__device__ __forceinline__ void cpa16(uint32_t dst, const void* src) {
    asm volatile("cp.async.cg.shared.global [%0], [%1], 16;" :: "r"(dst), "l"(src));
}
#define CP_COMMIT() asm volatile("cp.async.commit_group;" ::: "memory")
#define CP_WAIT1()  asm volatile("cp.async.wait_group 1;" ::: "memory")
#define CP_WAIT0()  asm volatile("cp.async.wait_group 0;" ::: "memory")

__device__ __forceinline__ void ldsm_x4(uint32_t* r, uint32_t addr) {
    asm volatile("ldmatrix.sync.aligned.m8n8.x4.shared.b16 {%0,%1,%2,%3}, [%4];"
                 : "=r"(r[0]), "=r"(r[1]), "=r"(r[2]), "=r"(r[3]) : "r"(addr));
}
__device__ __forceinline__ void ldsm_x4t(uint32_t* r, uint32_t addr) {
    asm volatile("ldmatrix.sync.aligned.m8n8.x4.trans.shared.b16 {%0,%1,%2,%3}, [%4];"
                 : "=r"(r[0]), "=r"(r[1]), "=r"(r[2]), "=r"(r[3]) : "r"(addr));
}
__device__ __forceinline__ void mma_bf16(float* d, const uint32_t* a, const uint32_t* b) {
    asm volatile(
        "mma.sync.aligned.m16n8k16.row.col.f32.bf16.bf16.f32 "
        "{%0,%1,%2,%3}, {%4,%5,%6,%7}, {%8,%9}, {%0,%1,%2,%3};"
        : "+f"(d[0]), "+f"(d[1]), "+f"(d[2]), "+f"(d[3])
        : "r"(a[0]), "r"(a[1]), "r"(a[2]), "r"(a[3]), "r"(b[0]), "r"(b[1]));
}
__device__ __forceinline__ void split2(float a, float b, uint32_t* hi, uint32_t* lo) {
    __nv_bfloat16 ha = __float2bfloat16(a), hb = __float2bfloat16(b);
    __nv_bfloat16 la = __float2bfloat16(a - __bfloat162float(ha));
    __nv_bfloat16 lb = __float2bfloat16(b - __bfloat162float(hb));
    *hi = (uint32_t)__bfloat16_as_ushort(ha) | ((uint32_t)__bfloat16_as_ushort(hb) << 16);
    *lo = (uint32_t)__bfloat16_as_ushort(la) | ((uint32_t)__bfloat16_as_ushort(lb) << 16);
}

// ---------------------------------------------------------------------------
// Kernel A: split fp32 -> (hi, lo) bf16, plain row-major
// ---------------------------------------------------------------------------
__global__ void __launch_bounds__(256) convert_split_kernel(
    const float* __restrict__ src, __nv_bfloat16* __restrict__ hi,
    __nv_bfloat16* __restrict__ lo, int nchunks)
{
    int idx = blockIdx.x * 256 + threadIdx.x;
    if (idx >= nchunks) return;
    size_t e = (size_t)idx * 8;

    const float4* p = (const float4*)(src + e);
    float4 a = p[0], b = p[1];
    float v[8] = {a.x, a.y, a.z, a.w, b.x, b.y, b.z, b.w};

    uint32_t hp[4], lp[4];
#pragma unroll
    for (int i = 0; i < 4; i++) split2(v[2*i], v[2*i+1], &hp[i], &lp[i]);
    *(uint4*)(hi + e) = make_uint4(hp[0], hp[1], hp[2], hp[3]);
    *(uint4*)(lo + e) = make_uint4(lp[0], lp[1], lp[2], lp[3]);
}

// ---------------------------------------------------------------------------
// Kernel B: HMMA GEMM  k = X @ Wk^T  (K = 3*768, bf16 split)
// CTA 128x128, 8 warps of 64x32, BK=64, 3-stage cp.async, XOR-swizzled smem,
// 2 CTAs/SM. Epilogue emits kh/kl bf16 HEAD-MAJOR [B, H, N, 64].
// ---------------------------------------------------------------------------
#define KTB_ 16384                 // 128 rows x 128B (64 bf16), swizzled
#define STAGEB_ (2 * KTB_)
#define NSTG_ 3
#define GEMM_SMEM_REQ (NSTG_ * STAGEB_)  // 98304

__device__ __forceinline__ void load_tile64(
    uint32_t aS, uint32_t bS, const char* Aseg, const char* Bseg,
    int mt, int nt, int kk, int tid)
{
#pragma unroll
    for (int i = 0; i < 4; i++) {
        int idx = tid + i * 256;            // 0..1023
        int row = idx >> 3, c = idx & 7;
        uint32_t sw = (uint32_t)((c ^ (row & 7)) * 16);
        cpa16(aS + row * 128 + sw,
              Aseg + ((size_t)(mt * 128 + row) * C_ + kk + c * 8) * 2);
    }
#pragma unroll
    for (int i = 0; i < 4; i++) {
        int idx = tid + i * 256;
        int row = idx >> 3, c = idx & 7;
        uint32_t sw = (uint32_t)((c ^ (row & 7)) * 16);
        cpa16(bS + row * 128 + sw,
              Bseg + ((size_t)(nt * 128 + row) * C_ + kk + c * 8) * 2);
    }
}

__global__ void __launch_bounds__(256, 2) k_gemm_mma(
    const __nv_bfloat16* __restrict__ xh, const __nv_bfloat16* __restrict__ xl,
    const __nv_bfloat16* __restrict__ wh, const __nv_bfloat16* __restrict__ wl,
    __nv_bfloat16* __restrict__ khg, __nv_bfloat16* __restrict__ klg)
{
    extern __shared__ char dsm[];
    const uint32_t sbase = smem_u32(dsm);

    const int tid  = threadIdx.x;
    const int lane = tid & 31;
    const int warp = tid >> 5;
    const int wm   = warp >> 2;      // 0..1
    const int wn   = warp & 3;       // 0..3
    const int nt   = blockIdx.x;
    const int mt   = blockIdx.y;

    const char* Asrc[KSEG_] = {(const char*)xh, (const char*)xh, (const char*)xl};
    const char* Bsrc[KSEG_] = {(const char*)wh, (const char*)wl, (const char*)wh};

    float acc[4][4][4];
#pragma unroll
    for (int mi = 0; mi < 4; mi++)
#pragma unroll
        for (int ni = 0; ni < 4; ni++)
#pragma unroll
            for (int i = 0; i < 4; i++) acc[mi][ni][i] = 0.0f;

    // prologue: stages 0,1 (chunks 0,1 — both seg 0)
#pragma unroll
    for (int s = 0; s < NSTG_ - 1; s++) {
        load_tile64(sbase + s * STAGEB_, sbase + s * STAGEB_ + KTB_,
                    Asrc[0], Bsrc[0], mt, nt, s * BK_, tid);
        CP_COMMIT();
    }

    // ldmatrix lane rows (swizzle applied per-access)
    const int arow_l = lane & 15;          // + wm*64 + mi*16
    const int agrp_l = lane >> 4;          // + 2h
    const int brow_l = (lane & 7) + ((lane >> 4) & 1) * 8;  // + wn*32 + pair*16
    const int bgrp_l = (lane >> 3) & 1;    // + 2h

    for (int kc = 0; kc < NCHUNK_TOT_; kc++) {
        CP_WAIT1();
        __syncthreads();

        int pf = kc + NSTG_ - 1;
        if (pf < NCHUNK_TOT_) {
            int seg = pf / CH_PER_SEG_;
            int kk  = (pf % CH_PER_SEG_) * BK_;
            int s   = pf % NSTG_;
            load_tile64(sbase + s * STAGEB_, sbase + s * STAGEB_ + KTB_,
                        Asrc[seg], Bsrc[seg], mt, nt, kk, tid);
        }
        CP_COMMIT();

        const uint32_t aS = sbase + (kc % NSTG_) * STAGEB_;
        const uint32_t bS = aS + KTB_;
#pragma unroll
        for (int h = 0; h < 4; h++) {
            uint32_t a[4][4], bq[2][4];
#pragma unroll
            for (int mi = 0; mi < 4; mi++) {
                int row = wm * 64 + mi * 16 + arow_l;
                int g   = (2 * h + agrp_l) ^ (row & 7);
                ldsm_x4(a[mi], aS + row * 128 + g * 16);
            }
#pragma unroll
            for (int pair = 0; pair < 2; pair++) {
                int row = wn * 32 + pair * 16 + brow_l;
                int g   = (2 * h + bgrp_l) ^ (row & 7);
                ldsm_x4(bq[pair], bS + row * 128 + g * 16);
            }
#pragma unroll
            for (int mi = 0; mi < 4; mi++)
#pragma unroll
                for (int ni = 0; ni < 4; ni++)
                    mma_bf16(acc[mi][ni], a[mi], bq[ni >> 1] + (ni & 1) * 2);
        }
        __syncthreads();
    }

    // epilogue: split to bf16 hi/lo, scatter head-major [B, H, N, 64]
#pragma unroll
    for (int mi = 0; mi < 4; mi++) {
#pragma unroll
        for (int ni = 0; ni < 4; ni++) {
            int r = mt * 128 + wm * 64 + mi * 16 + (lane >> 2);
            int c = nt * 128 + wn * 32 + ni * 8 + (lane & 3) * 2;
            int b = r >> 12, n = r & (N_ - 1);
            int hh = c >> 6, d = c & 63;
            size_t addr = (((size_t)b * H_ + hh) * N_ + n) * HD_ + d;
            uint32_t h01, l01, h23, l23;
            split2(acc[mi][ni][0], acc[mi][ni][1], &h01, &l01);
            split2(acc[mi][ni][2], acc[mi][ni][3], &h23, &l23);
            *(uint32_t*)&khg[addr] = h01;
            *(uint32_t*)&klg[addr] = l01;
            *(uint32_t*)&khg[addr + 8 * HD_] = h23;   // row r+8
            *(uint32_t*)&klg[addr + 8 * HD_] = l23;
        }
    }
}

// ---------------------------------------------------------------------------
// Kernel 2: small GEMM  C[M,N] = A[M,K]*B[N,K]^T (+bias)
// ---------------------------------------------------------------------------
__global__ void __launch_bounds__(256) small_gemm_nt(
    const float* __restrict__ A, const float* __restrict__ Bm,
    const float* __restrict__ bias, float* __restrict__ C,
    int M, int N, int K)
{
    __shared__ float AsT[16][17];
    __shared__ float BsT[16][65];

    const int t  = threadIdx.x;
    const int n0 = blockIdx.x * 64;
    const int m0 = blockIdx.y * 16;
    const int r0 = t >> 6;
    const int c  = t & 63;

    float acc[4] = {0.f, 0.f, 0.f, 0.f};

    for (int k0 = 0; k0 < K; k0 += 16) {
        __syncthreads();
        { int mm = t >> 4, kk = t & 15;
          AsT[kk][mm] = A[(long)(m0 + mm) * K + k0 + kk]; }
        { int nn = t >> 2, k4 = (t & 3) * 4;
          float4 v = *(const float4*)&Bm[(long)(n0 + nn) * K + k0 + k4];
          BsT[k4 + 0][nn] = v.x; BsT[k4 + 1][nn] = v.y;
          BsT[k4 + 2][nn] = v.z; BsT[k4 + 3][nn] = v.w; }
        __syncthreads();
#pragma unroll
        for (int kk = 0; kk < 16; kk++) {
            float bb = BsT[kk][c];
            acc[0] = fmaf(AsT[kk][r0 +  0], bb, acc[0]);
            acc[1] = fmaf(AsT[kk][r0 +  4], bb, acc[1]);
            acc[2] = fmaf(AsT[kk][r0 +  8], bb, acc[2]);
            acc[3] = fmaf(AsT[kk][r0 + 12], bb, acc[3]);
        }
    }
    float bv = bias ? bias[n0 + c] : 0.0f;
#pragma unroll
    for (int i = 0; i < 4; i++)
        C[(long)(m0 + r0 + 4 * i) * N + n0 + c] = acc[i] + bv;
}

// ---------------------------------------------------------------------------
// Hopfield step via HMMA (flash-attn v2 structure), split-N. (unchanged)
// ---------------------------------------------------------------------------
__global__ void hop_init_q(const float* __restrict__ q0, float* __restrict__ qst)
{
    int bh = blockIdx.x, h = bh % H_;
    for (int i = threadIdx.x; i < L_ * HD_; i += 256) {
        int l = i >> 6, d = i & 63;
        qst[bh * (L_ * HD_) + i] = q0[l * C_ + h * HD_ + d];
    }
}

#define KROW_ 144                       // 64 bf16 = 128B + 16B pad
#define KTILE_PAD_ (128 * KROW_)        // 18432
#define HOP_SMEM_ (4 * KTILE_PAD_ + 2 * L_ * KROW_)   // 78336

__global__ void __launch_bounds__(256, 2) hop_partial(
    const float* __restrict__ qst,
    const __nv_bfloat16* __restrict__ khg, const __nv_bfloat16* __restrict__ klg,
    float* __restrict__ m_part, float* __restrict__ z_part,
    float* __restrict__ acc_part)
{
    extern __shared__ __align__(16) char hsm8[];
    __shared__ float mw[NWARP_][L_];
    __shared__ float zw[NWARP_][L_];
    __shared__ float Mg[L_];

    const int t     = threadIdx.x;
    const int warp  = t >> 5;
    const int lane  = t & 31;
    const int split = blockIdx.x;
    const int bh    = blockIdx.y;
    const uint32_t sb  = smem_u32(hsm8);
    const uint32_t KH0 = sb;
    const uint32_t KL0 = sb + 2 * KTILE_PAD_;
    const uint32_t QHo = sb + 4 * KTILE_PAD_;
    const uint32_t QLo = QHo + L_ * KROW_;

    const char* ksrc_h = (const char*)(khg + ((size_t)bh * N_ + split * (N_ / NS_)) * HD_);
    const char* ksrc_l = (const char*)(klg + ((size_t)bh * N_ + split * (N_ / NS_)) * HD_);

    // prefetch tile 0 (kh+kl, 16KB each, into padded rows)
#pragma unroll
    for (int i = 0; i < 4; i++) {
        int idx = t + i * 256;                 // 0..1023
        int row = idx >> 3, c = idx & 7;
        cpa16(KH0 + row * KROW_ + c * 16, ksrc_h + (size_t)idx * 16);
        cpa16(KL0 + row * KROW_ + c * 16, ksrc_l + (size_t)idx * 16);
    }
    CP_COMMIT();

    // q: scale, split, park in padded smem (ldmatrix-ready)
    {
        float4 v = ((const float4*)(qst + bh * (L_ * HD_)))[t];
        int e = t * 4, r = e >> 6, d = e & 63;
        uint32_t h01, l01, h23, l23;
        split2(v.x * 0.125f, v.y * 0.125f, &h01, &l01);
        split2(v.z * 0.125f, v.w * 0.125f, &h23, &l23);
        char* qh = hsm8 + 4 * KTILE_PAD_ + r * KROW_ + d * 2;
        char* ql = qh + L_ * KROW_;
        *(uint32_t*)qh = h01; *(uint32_t*)(qh + 4) = h23;
        *(uint32_t*)ql = l01; *(uint32_t*)(ql + 4) = l23;
    }

    float S[2][4], O[8][4];
#pragma unroll
    for (int i = 0; i < 8; i++)
#pragma unroll
        for (int j = 0; j < 4; j++) O[i][j] = 0.0f;
    float m0 = -1e30f, m1 = -1e30f, Z0 = 0.0f, Z1 = 0.0f;

    const uint32_t qa_off = (uint32_t)((lane & 15) * KROW_ + (lane >> 4) * 16);
    const uint32_t kb_off = (uint32_t)((warp * 16 + ((lane >> 4) & 1) * 8 + (lane & 7)) * KROW_
                                       + ((lane >> 3) & 1) * 16);
    const uint32_t v_off  = (uint32_t)((warp * 16 + (lane & 15)) * KROW_ + (lane >> 4) * 16);

    for (int tile = 0; tile < NT_SPL_; tile++) {
        if (tile + 1 < NT_SPL_) {
            uint32_t khd = KH0 + ((tile + 1) & 1) * KTILE_PAD_;
            uint32_t kld = KL0 + ((tile + 1) & 1) * KTILE_PAD_;
            const char* sh = ksrc_h + (size_t)(tile + 1) * (TN_ * HD_ * 2);
            const char* sl = ksrc_l + (size_t)(tile + 1) * (TN_ * HD_ * 2);
#pragma unroll
            for (int i = 0; i < 4; i++) {
                int idx = t + i * 256;
                int row = idx >> 3, c = idx & 7;
                cpa16(khd + row * KROW_ + c * 16, sh + (size_t)idx * 16);
                cpa16(kld + row * KROW_ + c * 16, sl + (size_t)idx * 16);
            }
            CP_COMMIT();
            CP_WAIT1();
        } else {
            CP_WAIT0();
        }
        __syncthreads();

        const uint32_t khb = KH0 + (tile & 1) * KTILE_PAD_;
        const uint32_t klb = KL0 + (tile & 1) * KTILE_PAD_;

        // ---- scores: S[2 ntiles][4], 3-term split ----
#pragma unroll
        for (int nt = 0; nt < 2; nt++)
#pragma unroll
            for (int i = 0; i < 4; i++) S[nt][i] = 0.0f;
#pragma unroll
        for (int kc = 0; kc < 4; kc++) {
            uint32_t qh4[4], ql4[4], bh4[4], bl4[4];
            ldsm_x4(qh4, QHo + qa_off + kc * 32);
            ldsm_x4(ql4, QLo + qa_off + kc * 32);
            ldsm_x4(bh4, khb + kb_off + kc * 32);
            ldsm_x4(bl4, klb + kb_off + kc * 32);
            mma_bf16(S[0], qh4, bh4);
            mma_bf16(S[1], qh4, bh4 + 2);
            mma_bf16(S[0], qh4, bl4);
            mma_bf16(S[1], qh4, bl4 + 2);
            mma_bf16(S[0], ql4, bh4);
            mma_bf16(S[1], ql4, bh4 + 2);
        }

        // ---- online softmax (rows r = lane>>2 and r+8) ----
        float mx0 = fmaxf(fmaxf(S[0][0], S[0][1]), fmaxf(S[1][0], S[1][1]));
        float mx1 = fmaxf(fmaxf(S[0][2], S[0][3]), fmaxf(S[1][2], S[1][3]));
        mx0 = fmaxf(mx0, __shfl_xor_sync(0xffffffffu, mx0, 1));
        mx0 = fmaxf(mx0, __shfl_xor_sync(0xffffffffu, mx0, 2));
        mx1 = fmaxf(mx1, __shfl_xor_sync(0xffffffffu, mx1, 1));
        mx1 = fmaxf(mx1, __shfl_xor_sync(0xffffffffu, mx1, 2));
        float mn0 = fmaxf(m0, mx0), mn1 = fmaxf(m1, mx1);
        float f0 = __expf(m0 - mn0), f1 = __expf(m1 - mn1);
        Z0 *= f0; Z1 *= f1;
#pragma unroll
        for (int nt = 0; nt < 8; nt++) {
            O[nt][0] *= f0; O[nt][1] *= f0;
            O[nt][2] *= f1; O[nt][3] *= f1;
        }
        float P00 = __expf(S[0][0] - mn0), P01 = __expf(S[0][1] - mn0);
        float P02 = __expf(S[0][2] - mn1), P03 = __expf(S[0][3] - mn1);
        float P10 = __expf(S[1][0] - mn0), P11 = __expf(S[1][1] - mn0);
        float P12 = __expf(S[1][2] - mn1), P13 = __expf(S[1][3] - mn1);
        Z0 += P00 + P01 + P10 + P11;
        Z1 += P02 + P03 + P12 + P13;
        uint32_t ph[4], pl[4];
        split2(P00, P01, &ph[0], &pl[0]);
        split2(P02, P03, &ph[1], &pl[1]);
        split2(P10, P11, &ph[2], &pl[2]);
        split2(P12, P13, &ph[3], &pl[3]);
        m0 = mn0; m1 = mn1;

        // ---- AV: O[8 hd-tiles][4] += P x V ----
#pragma unroll
        for (int hp = 0; hp < 4; hp++) {
            uint32_t vh4[4], vl4[4];
            ldsm_x4t(vh4, khb + v_off + hp * 32);
            ldsm_x4t(vl4, klb + v_off + hp * 32);
            mma_bf16(O[2*hp],     ph, vh4);
            mma_bf16(O[2*hp],     ph, vl4);
            mma_bf16(O[2*hp],     pl, vh4);
            mma_bf16(O[2*hp + 1], ph, vh4 + 2);
            mma_bf16(O[2*hp + 1], ph, vl4 + 2);
            mma_bf16(O[2*hp + 1], pl, vh4 + 2);
        }
        __syncthreads();
    }

    // ---- block combine ----
    Z0 += __shfl_xor_sync(0xffffffffu, Z0, 1);
    Z0 += __shfl_xor_sync(0xffffffffu, Z0, 2);
    Z1 += __shfl_xor_sync(0xffffffffu, Z1, 1);
    Z1 += __shfl_xor_sync(0xffffffffu, Z1, 2);
    const int r = lane >> 2;
    if ((lane & 3) == 0) {
        mw[warp][r]     = m0;  mw[warp][r + 8] = m1;
        zw[warp][r]     = Z0;  zw[warp][r + 8] = Z1;
    }
    __syncthreads();
    if (t < L_) {
        float M = -1e30f;
#pragma unroll
        for (int w = 0; w < NWARP_; w++) M = fmaxf(M, mw[w][t]);
        Mg[t] = M;
        float Zt = 0.0f;
#pragma unroll
        for (int w = 0; w < NWARP_; w++)
            Zt += zw[w][t] * __expf(mw[w][t] - M);
        int o = (bh * NS_ + split) * L_ + t;
        m_part[o] = M;
        z_part[o] = Zt;
    }
    __syncthreads();
    {
        float g0 = __expf(m0 - Mg[r]);
        float g1 = __expf(m1 - Mg[r + 8]);
        float* cb = (float*)hsm8 + warp * (L_ * HD_);
        int cbase = (lane & 3) * 2;
#pragma unroll
        for (int nt = 0; nt < 8; nt++) {
            int col = nt * 8 + cbase;
            *(float2*)&cb[r * HD_ + col]       = make_float2(O[nt][0] * g0, O[nt][1] * g0);
            *(float2*)&cb[(r + 8) * HD_ + col] = make_float2(O[nt][2] * g1, O[nt][3] * g1);
        }
    }
    __syncthreads();
    {
        const float* call = (const float*)hsm8;
        size_t ob = (size_t)(bh * NS_ + split) * (L_ * HD_);
        for (int i = t; i < L_ * HD_; i += 256) {
            float s = 0.0f;
#pragma unroll
            for (int w = 0; w < NWARP_; w++) s += call[w * (L_ * HD_) + i];
            acc_part[ob + i] = s;
        }
    }
}

__global__ void hop_combine(
    const float* __restrict__ m_part, const float* __restrict__ z_part,
    const float* __restrict__ acc_part, float* __restrict__ qdst, int final_mode)
{
    __shared__ float F[NS_][L_];
    __shared__ float Zs[L_];

    const int bh = blockIdx.x;
    const int b = bh / H_, h = bh % H_;
    const int t = threadIdx.x;

    if (t < L_) {
        float mv[NS_];
        float M = 0.0f;   // softmax_1 clamp at 0
#pragma unroll
        for (int i = 0; i < NS_; i++) {
            mv[i] = m_part[(bh * NS_ + i) * L_ + t];
            M = fmaxf(M, mv[i]);
        }
        float Zt = __expf(-M);   // phantom logit 0
#pragma unroll
        for (int i = 0; i < NS_; i++) {
            float f = __expf(mv[i] - M);
            F[i][t] = f;
            Zt += z_part[(bh * NS_ + i) * L_ + t] * f;
        }
        Zs[t] = Zt;
    }
    __syncthreads();

    for (int idx = t; idx < L_ * HD_; idx += 256) {
        int l = idx >> 6, d = idx & 63;
        float sum = 0.0f;
#pragma unroll
        for (int i = 0; i < NS_; i++)
            sum += acc_part[(size_t)(bh * NS_ + i) * (L_ * HD_) + idx] * F[i][l];
        sum /= Zs[l];
        if (final_mode)
            qdst[((size_t)b * L_ + l) * C_ + h * HD_ + d] = sum;
        else
            qdst[bh * (L_ * HD_) + idx] = sum;
    }
}

// ---------------------------------------------------------------------------
// Launch
// ---------------------------------------------------------------------------
extern "C" void kernel_launch(void* const* d_in, const int* in_sizes, int n_in,
                              void* d_out, int out_size)
{
    const float* x     = (const float*)d_in[0];
    const float* query = (const float*)d_in[1];
    const float* Wq    = (const float*)d_in[2];
    const float* Wk    = (const float*)d_in[3];
    const float* Wv    = (const float*)d_in[4];
    const float* Wproj = (const float*)d_in[5];
    const float* bproj = (const float*)d_in[6];
    float* out = (float*)d_out;

    float *q0_scr, *qf_scr, *tmp_scr, *q_state, *m_part, *z_part, *acc_part;
    __nv_bfloat16 *xh, *xl, *wh, *wl, *khg, *klg;
    cudaGetSymbolAddress((void**)&q0_scr, g_q0_scr);
    cudaGetSymbolAddress((void**)&qf_scr, g_qf_scr);
    cudaGetSymbolAddress((void**)&tmp_scr, g_tmp_scr);
    cudaGetSymbolAddress((void**)&q_state, g_q_state);
    cudaGetSymbolAddress((void**)&m_part, g_m_part);
    cudaGetSymbolAddress((void**)&z_part, g_z_part);
    cudaGetSymbolAddress((void**)&acc_part, g_acc_part);
    cudaGetSymbolAddress((void**)&xh, g_xh);
    cudaGetSymbolAddress((void**)&xl, g_xl);
    cudaGetSymbolAddress((void**)&wh, g_wh);
    cudaGetSymbolAddress((void**)&wl, g_wl);
    cudaGetSymbolAddress((void**)&khg, g_kh);
    cudaGetSymbolAddress((void**)&klg, g_kl);

    static bool attr_set = false;
    if (!attr_set) {
        cudaFuncSetAttribute(k_gemm_mma, cudaFuncAttributeMaxDynamicSharedMemorySize,
                             GEMM_SMEM_REQ);
        cudaFuncSetAttribute(hop_partial, cudaFuncAttributeMaxDynamicSharedMemorySize,
                             HOP_SMEM_);
        attr_set = true;
    }

    // split/convert x and Wk into row-major bf16 hi/lo
    {
        int nch_x = (MROWS_ * C_) / 8;
        convert_split_kernel<<<(nch_x + 255) / 256, 256>>>(x, xh, xl, nch_x);
        int nch_w = (C_ * C_) / 8;
        convert_split_kernel<<<(nch_w + 255) / 256, 256>>>(Wk, wh, wl, nch_w);
    }
    // q0 = query @ Wq^T
    small_gemm_nt<<<dim3(C_ / 64, 1), 256>>>(query, Wq, nullptr, q0_scr, L_, C_, C_);
    // k = x @ Wk^T via HMMA -> kh/kl bf16 head-major
    k_gemm_mma<<<dim3(C_ / 128, MROWS_ / 128), 256, GEMM_SMEM_REQ>>>(xh, xl, wh, wl, khg, klg);
    // 3-step Hopfield attention (HMMA flash)
    hop_init_q<<<BH_, 256>>>(q0_scr, q_state);
    for (int s = 0; s < STEPS_; s++) {
        hop_partial<<<dim3(NS_, BH_), 256, HOP_SMEM_>>>(
            q_state, khg, klg, m_part, z_part, acc_part);
        hop_combine<<<BH_, 256>>>(m_part, z_part, acc_part,
                                  (s == STEPS_ - 1) ? qf_scr : q_state,
                                  (s == STEPS_ - 1) ? 1 : 0);
    }
    // out projections
    small_gemm_nt<<<dim3(C_ / 64, (B_ * L_) / 16), 256>>>(
        qf_scr, Wv, nullptr, tmp_scr, B_ * L_, C_, C_);
    small_gemm_nt<<<dim3(C_ / 64, (B_ * L_) / 16), 256>>>(
        tmp_scr, Wproj, bproj, out, B_ * L_, C_, C_);
}

// round 8
// speedup vs baseline: 5.5157x; 1.0315x over previous
#include <cuda_runtime.h>
#include <cuda_bf16.h>
#include <cstdint>

// ---------------------------------------------------------------------------
// Shapes (fixed by the problem)
// ---------------------------------------------------------------------------
#define B_  16
#define N_  4096
#define C_  768
#define L_  16
#define H_  12
#define HD_ 64
#define STEPS_ 3
#define BH_ (B_ * H_)               // 192

#define MROWS_ (B_ * N_)            // 65536
#define KSEG_  3                    // hi*hi, hi*lo, lo*hi
#define BK_    64
#define CH_PER_SEG_ (C_ / BK_)      // 12
#define NCHUNK_TOT_ (KSEG_ * CH_PER_SEG_)  // 36

// Hopfield split
#define TN_ 128
#define NWARP_ 8
#define NS_ 4
#define NT_SPL_ (N_ / NS_ / TN_)    // 8 tiles per split

// ---------------------------------------------------------------------------
// Scratch (__device__ globals)
// ---------------------------------------------------------------------------
__device__ __align__(16) __nv_bfloat16 g_kh[(size_t)BH_ * N_ * HD_];
__device__ __align__(16) __nv_bfloat16 g_kl[(size_t)BH_ * N_ * HD_];
__device__ __align__(16) __nv_bfloat16 g_xh[(size_t)MROWS_ * C_];
__device__ __align__(16) __nv_bfloat16 g_xl[(size_t)MROWS_ * C_];
__device__ __align__(16) __nv_bfloat16 g_wh[(size_t)C_ * C_];
__device__ __align__(16) __nv_bfloat16 g_wl[(size_t)C_ * C_];
__device__ float g_q0_scr[L_ * C_];
__device__ float g_qf_scr[B_ * L_ * C_];
__device__ float g_tmp_scr[B_ * L_ * C_];
__device__ __align__(16) float g_q_state[BH_ * L_ * HD_];
__device__ float g_m_part[BH_ * NS_ * L_];
__device__ float g_z_part[BH_ * NS_ * L_];
__device__ __align__(16) float g_acc_part[(size_t)BH_ * NS_ * L_ * HD_];

// ---------------------------------------------------------------------------
// helpers
// ---------------------------------------------------------------------------
__device__ __forceinline__ uint32_t smem_u32(const void* p) {
    uint32_t a;
    asm("{ .reg .u64 t; cvta.to.shared.u64 t, %1; cvt.u32.u64 %0, t; }" : "=r"(a) : "l"(p));
    return a;
}
__device__ __forceinline__ void cpa16(uint32_t dst, const void* src) {
    asm volatile("cp.async.cg.shared.global [%0], [%1], 16;" :: "r"(dst), "l"(src));
}
#define CP_COMMIT() asm volatile("cp.async.commit_group;" ::: "memory")
#define CP_WAIT1()  asm volatile("cp.async.wait_group 1;" ::: "memory")
#define CP_WAIT0()  asm volatile("cp.async.wait_group 0;" ::: "memory")

__device__ __forceinline__ void ldsm_x4(uint32_t* r, uint32_t addr) {
    asm volatile("ldmatrix.sync.aligned.m8n8.x4.shared.b16 {%0,%1,%2,%3}, [%4];"
                 : "=r"(r[0]), "=r"(r[1]), "=r"(r[2]), "=r"(r[3]) : "r"(addr));
}
__device__ __forceinline__ void ldsm_x4t(uint32_t* r, uint32_t addr) {
    asm volatile("ldmatrix.sync.aligned.m8n8.x4.trans.shared.b16 {%0,%1,%2,%3}, [%4];"
                 : "=r"(r[0]), "=r"(r[1]), "=r"(r[2]), "=r"(r[3]) : "r"(addr));
}
__device__ __forceinline__ void mma_bf16(float* d, const uint32_t* a, const uint32_t* b) {
    asm volatile(
        "mma.sync.aligned.m16n8k16.row.col.f32.bf16.bf16.f32 "
        "{%0,%1,%2,%3}, {%4,%5,%6,%7}, {%8,%9}, {%0,%1,%2,%3};"
        : "+f"(d[0]), "+f"(d[1]), "+f"(d[2]), "+f"(d[3])
        : "r"(a[0]), "r"(a[1]), "r"(a[2]), "r"(a[3]), "r"(b[0]), "r"(b[1]));
}
__device__ __forceinline__ void split2(float a, float b, uint32_t* hi, uint32_t* lo) {
    __nv_bfloat16 ha = __float2bfloat16(a), hb = __float2bfloat16(b);
    __nv_bfloat16 la = __float2bfloat16(a - __bfloat162float(ha));
    __nv_bfloat16 lb = __float2bfloat16(b - __bfloat162float(hb));
    *hi = (uint32_t)__bfloat16_as_ushort(ha) | ((uint32_t)__bfloat16_as_ushort(hb) << 16);
    *lo = (uint32_t)__bfloat16_as_ushort(la) | ((uint32_t)__bfloat16_as_ushort(lb) << 16);
}

// ---------------------------------------------------------------------------
// Kernel A: split fp32 -> (hi, lo) bf16, plain row-major
// ---------------------------------------------------------------------------
__global__ void __launch_bounds__(256) convert_split_kernel(
    const float* __restrict__ src, __nv_bfloat16* __restrict__ hi,
    __nv_bfloat16* __restrict__ lo, int nchunks)
{
    int idx = blockIdx.x * 256 + threadIdx.x;
    if (idx >= nchunks) return;
    size_t e = (size_t)idx * 8;

    const float4* p = (const float4*)(src + e);
    float4 a = p[0], b = p[1];
    float v[8] = {a.x, a.y, a.z, a.w, b.x, b.y, b.z, b.w};

    uint32_t hp[4], lp[4];
#pragma unroll
    for (int i = 0; i < 4; i++) split2(v[2*i], v[2*i+1], &hp[i], &lp[i]);
    *(uint4*)(hi + e) = make_uint4(hp[0], hp[1], hp[2], hp[3]);
    *(uint4*)(lo + e) = make_uint4(lp[0], lp[1], lp[2], lp[3]);
}

// ---------------------------------------------------------------------------
// Kernel B: HMMA GEMM  k = X @ Wk^T  (K = 3*768, bf16 split)
// CTA 128x128 with 4 warps of 64x64, BK=64, 3-stage cp.async, XOR swizzle,
// 2 CTAs/SM, fragment double-buffering across h. One barrier per chunk.
// Epilogue emits kh/kl bf16 HEAD-MAJOR [B, H, N, 64].
// ---------------------------------------------------------------------------
#define KTB_ 16384                 // 128 rows x 128B (64 bf16), swizzled
#define STAGEB_ (2 * KTB_)
#define NSTG_ 3
#define GEMM_SMEM_REQ (NSTG_ * STAGEB_)  // 98304
#define GT_ 128                    // threads per CTA

__device__ __forceinline__ void load_tile64(
    uint32_t aS, uint32_t bS, const char* Aseg, const char* Bseg,
    int mt, int nt, int kk, int tid)
{
#pragma unroll
    for (int i = 0; i < 8; i++) {
        int idx = tid + i * GT_;            // 0..1023
        int row = idx >> 3, c = idx & 7;
        uint32_t sw = (uint32_t)((c ^ (row & 7)) * 16);
        cpa16(aS + row * 128 + sw,
              Aseg + ((size_t)(mt * 128 + row) * C_ + kk + c * 8) * 2);
    }
#pragma unroll
    for (int i = 0; i < 8; i++) {
        int idx = tid + i * GT_;
        int row = idx >> 3, c = idx & 7;
        uint32_t sw = (uint32_t)((c ^ (row & 7)) * 16);
        cpa16(bS + row * 128 + sw,
              Bseg + ((size_t)(nt * 128 + row) * C_ + kk + c * 8) * 2);
    }
}

struct Frag { uint32_t a[4][4]; uint32_t b[4][4]; };

__device__ __forceinline__ void load_frag(
    Frag& f, uint32_t aS, uint32_t bS, int h,
    int wm, int wn, int arow_l, int agrp_l, int brow_l, int bgrp_l)
{
#pragma unroll
    for (int mi = 0; mi < 4; mi++) {
        int row = wm * 64 + mi * 16 + arow_l;
        int g   = (2 * h + agrp_l) ^ (row & 7);
        ldsm_x4(f.a[mi], aS + row * 128 + g * 16);
    }
#pragma unroll
    for (int p = 0; p < 4; p++) {
        int row = wn * 64 + p * 16 + brow_l;
        int g   = (2 * h + bgrp_l) ^ (row & 7);
        ldsm_x4(f.b[p], bS + row * 128 + g * 16);
    }
}

__global__ void __launch_bounds__(GT_, 2) k_gemm_mma(
    const __nv_bfloat16* __restrict__ xh, const __nv_bfloat16* __restrict__ xl,
    const __nv_bfloat16* __restrict__ wh, const __nv_bfloat16* __restrict__ wl,
    __nv_bfloat16* __restrict__ khg, __nv_bfloat16* __restrict__ klg)
{
    extern __shared__ char dsm[];
    const uint32_t sbase = smem_u32(dsm);

    const int tid  = threadIdx.x;
    const int lane = tid & 31;
    const int warp = tid >> 5;       // 0..3
    const int wm   = warp >> 1;      // 0..1
    const int wn   = warp & 1;       // 0..1
    const int nt   = blockIdx.x;
    const int mt   = blockIdx.y;

    const char* Asrc[KSEG_] = {(const char*)xh, (const char*)xh, (const char*)xl};
    const char* Bsrc[KSEG_] = {(const char*)wh, (const char*)wl, (const char*)wh};

    float acc[4][8][4];
#pragma unroll
    for (int mi = 0; mi < 4; mi++)
#pragma unroll
        for (int ni = 0; ni < 8; ni++)
#pragma unroll
            for (int i = 0; i < 4; i++) acc[mi][ni][i] = 0.0f;

    // prologue: stages 0,1 (chunks 0,1 — both seg 0)
#pragma unroll
    for (int s = 0; s < NSTG_ - 1; s++) {
        load_tile64(sbase + s * STAGEB_, sbase + s * STAGEB_ + KTB_,
                    Asrc[0], Bsrc[0], mt, nt, s * BK_, tid);
        CP_COMMIT();
    }

    const int arow_l = lane & 15;
    const int agrp_l = lane >> 4;
    const int brow_l = (lane & 7) + ((lane >> 4) & 1) * 8;
    const int bgrp_l = (lane >> 3) & 1;

    Frag fr[2];

    for (int kc = 0; kc < NCHUNK_TOT_; kc++) {
        CP_WAIT1();
        __syncthreads();   // single barrier: orders prior compute vs new loads

        int pf = kc + NSTG_ - 1;
        if (pf < NCHUNK_TOT_) {
            int seg = pf / CH_PER_SEG_;
            int kk  = (pf % CH_PER_SEG_) * BK_;
            int s   = pf % NSTG_;
            load_tile64(sbase + s * STAGEB_, sbase + s * STAGEB_ + KTB_,
                        Asrc[seg], Bsrc[seg], mt, nt, kk, tid);
        }
        CP_COMMIT();

        const uint32_t aS = sbase + (kc % NSTG_) * STAGEB_;
        const uint32_t bS = aS + KTB_;

        load_frag(fr[0], aS, bS, 0, wm, wn, arow_l, agrp_l, brow_l, bgrp_l);
#pragma unroll
        for (int h = 0; h < 4; h++) {
            if (h < 3)
                load_frag(fr[(h + 1) & 1], aS, bS, h + 1,
                          wm, wn, arow_l, agrp_l, brow_l, bgrp_l);
            const Frag& f = fr[h & 1];
#pragma unroll
            for (int mi = 0; mi < 4; mi++)
#pragma unroll
                for (int ni = 0; ni < 8; ni++)
                    mma_bf16(acc[mi][ni], f.a[mi], f.b[ni >> 1] + (ni & 1) * 2);
        }
    }

    // epilogue: split to bf16 hi/lo, scatter head-major [B, H, N, 64]
#pragma unroll
    for (int mi = 0; mi < 4; mi++) {
#pragma unroll
        for (int ni = 0; ni < 8; ni++) {
            int r = mt * 128 + wm * 64 + mi * 16 + (lane >> 2);
            int c = nt * 128 + wn * 64 + ni * 8 + (lane & 3) * 2;
            int b = r >> 12, n = r & (N_ - 1);
            int hh = c >> 6, d = c & 63;
            size_t addr = (((size_t)b * H_ + hh) * N_ + n) * HD_ + d;
            uint32_t h01, l01, h23, l23;
            split2(acc[mi][ni][0], acc[mi][ni][1], &h01, &l01);
            split2(acc[mi][ni][2], acc[mi][ni][3], &h23, &l23);
            *(uint32_t*)&khg[addr] = h01;
            *(uint32_t*)&klg[addr] = l01;
            *(uint32_t*)&khg[addr + 8 * HD_] = h23;   // row r+8
            *(uint32_t*)&klg[addr + 8 * HD_] = l23;
        }
    }
}

// ---------------------------------------------------------------------------
// Kernel 2: small GEMM  C[M,N] = A[M,K]*B[N,K]^T (+bias)
// ---------------------------------------------------------------------------
__global__ void __launch_bounds__(256) small_gemm_nt(
    const float* __restrict__ A, const float* __restrict__ Bm,
    const float* __restrict__ bias, float* __restrict__ C,
    int M, int N, int K)
{
    __shared__ float AsT[16][17];
    __shared__ float BsT[16][65];

    const int t  = threadIdx.x;
    const int n0 = blockIdx.x * 64;
    const int m0 = blockIdx.y * 16;
    const int r0 = t >> 6;
    const int c  = t & 63;

    float acc[4] = {0.f, 0.f, 0.f, 0.f};

    for (int k0 = 0; k0 < K; k0 += 16) {
        __syncthreads();
        { int mm = t >> 4, kk = t & 15;
          AsT[kk][mm] = A[(long)(m0 + mm) * K + k0 + kk]; }
        { int nn = t >> 2, k4 = (t & 3) * 4;
          float4 v = *(const float4*)&Bm[(long)(n0 + nn) * K + k0 + k4];
          BsT[k4 + 0][nn] = v.x; BsT[k4 + 1][nn] = v.y;
          BsT[k4 + 2][nn] = v.z; BsT[k4 + 3][nn] = v.w; }
        __syncthreads();
#pragma unroll
        for (int kk = 0; kk < 16; kk++) {
            float bb = BsT[kk][c];
            acc[0] = fmaf(AsT[kk][r0 +  0], bb, acc[0]);
            acc[1] = fmaf(AsT[kk][r0 +  4], bb, acc[1]);
            acc[2] = fmaf(AsT[kk][r0 +  8], bb, acc[2]);
            acc[3] = fmaf(AsT[kk][r0 + 12], bb, acc[3]);
        }
    }
    float bv = bias ? bias[n0 + c] : 0.0f;
#pragma unroll
    for (int i = 0; i < 4; i++)
        C[(long)(m0 + r0 + 4 * i) * N + n0 + c] = acc[i] + bv;
}

// ---------------------------------------------------------------------------
// Hopfield step via HMMA (flash-attn v2 structure), split-N. (unchanged)
// ---------------------------------------------------------------------------
__global__ void hop_init_q(const float* __restrict__ q0, float* __restrict__ qst)
{
    int bh = blockIdx.x, h = bh % H_;
    for (int i = threadIdx.x; i < L_ * HD_; i += 256) {
        int l = i >> 6, d = i & 63;
        qst[bh * (L_ * HD_) + i] = q0[l * C_ + h * HD_ + d];
    }
}

#define KROW_ 144                       // 64 bf16 = 128B + 16B pad
#define KTILE_PAD_ (128 * KROW_)        // 18432
#define HOP_SMEM_ (4 * KTILE_PAD_ + 2 * L_ * KROW_)   // 78336

__global__ void __launch_bounds__(256, 2) hop_partial(
    const float* __restrict__ qst,
    const __nv_bfloat16* __restrict__ khg, const __nv_bfloat16* __restrict__ klg,
    float* __restrict__ m_part, float* __restrict__ z_part,
    float* __restrict__ acc_part)
{
    extern __shared__ __align__(16) char hsm8[];
    __shared__ float mw[NWARP_][L_];
    __shared__ float zw[NWARP_][L_];
    __shared__ float Mg[L_];

    const int t     = threadIdx.x;
    const int warp  = t >> 5;
    const int lane  = t & 31;
    const int split = blockIdx.x;
    const int bh    = blockIdx.y;
    const uint32_t sb  = smem_u32(hsm8);
    const uint32_t KH0 = sb;
    const uint32_t KL0 = sb + 2 * KTILE_PAD_;
    const uint32_t QHo = sb + 4 * KTILE_PAD_;
    const uint32_t QLo = QHo + L_ * KROW_;

    const char* ksrc_h = (const char*)(khg + ((size_t)bh * N_ + split * (N_ / NS_)) * HD_);
    const char* ksrc_l = (const char*)(klg + ((size_t)bh * N_ + split * (N_ / NS_)) * HD_);

    // prefetch tile 0
#pragma unroll
    for (int i = 0; i < 4; i++) {
        int idx = t + i * 256;
        int row = idx >> 3, c = idx & 7;
        cpa16(KH0 + row * KROW_ + c * 16, ksrc_h + (size_t)idx * 16);
        cpa16(KL0 + row * KROW_ + c * 16, ksrc_l + (size_t)idx * 16);
    }
    CP_COMMIT();

    // q: scale, split, park in padded smem
    {
        float4 v = ((const float4*)(qst + bh * (L_ * HD_)))[t];
        int e = t * 4, r = e >> 6, d = e & 63;
        uint32_t h01, l01, h23, l23;
        split2(v.x * 0.125f, v.y * 0.125f, &h01, &l01);
        split2(v.z * 0.125f, v.w * 0.125f, &h23, &l23);
        char* qh = hsm8 + 4 * KTILE_PAD_ + r * KROW_ + d * 2;
        char* ql = qh + L_ * KROW_;
        *(uint32_t*)qh = h01; *(uint32_t*)(qh + 4) = h23;
        *(uint32_t*)ql = l01; *(uint32_t*)(ql + 4) = l23;
    }

    float S[2][4], O[8][4];
#pragma unroll
    for (int i = 0; i < 8; i++)
#pragma unroll
        for (int j = 0; j < 4; j++) O[i][j] = 0.0f;
    float m0 = -1e30f, m1 = -1e30f, Z0 = 0.0f, Z1 = 0.0f;

    const uint32_t qa_off = (uint32_t)((lane & 15) * KROW_ + (lane >> 4) * 16);
    const uint32_t kb_off = (uint32_t)((warp * 16 + ((lane >> 4) & 1) * 8 + (lane & 7)) * KROW_
                                       + ((lane >> 3) & 1) * 16);
    const uint32_t v_off  = (uint32_t)((warp * 16 + (lane & 15)) * KROW_ + (lane >> 4) * 16);

    for (int tile = 0; tile < NT_SPL_; tile++) {
        if (tile + 1 < NT_SPL_) {
            uint32_t khd = KH0 + ((tile + 1) & 1) * KTILE_PAD_;
            uint32_t kld = KL0 + ((tile + 1) & 1) * KTILE_PAD_;
            const char* sh = ksrc_h + (size_t)(tile + 1) * (TN_ * HD_ * 2);
            const char* sl = ksrc_l + (size_t)(tile + 1) * (TN_ * HD_ * 2);
#pragma unroll
            for (int i = 0; i < 4; i++) {
                int idx = t + i * 256;
                int row = idx >> 3, c = idx & 7;
                cpa16(khd + row * KROW_ + c * 16, sh + (size_t)idx * 16);
                cpa16(kld + row * KROW_ + c * 16, sl + (size_t)idx * 16);
            }
            CP_COMMIT();
            CP_WAIT1();
        } else {
            CP_WAIT0();
        }
        __syncthreads();

        const uint32_t khb = KH0 + (tile & 1) * KTILE_PAD_;
        const uint32_t klb = KL0 + (tile & 1) * KTILE_PAD_;

#pragma unroll
        for (int nt = 0; nt < 2; nt++)
#pragma unroll
            for (int i = 0; i < 4; i++) S[nt][i] = 0.0f;
#pragma unroll
        for (int kc = 0; kc < 4; kc++) {
            uint32_t qh4[4], ql4[4], bh4[4], bl4[4];
            ldsm_x4(qh4, QHo + qa_off + kc * 32);
            ldsm_x4(ql4, QLo + qa_off + kc * 32);
            ldsm_x4(bh4, khb + kb_off + kc * 32);
            ldsm_x4(bl4, klb + kb_off + kc * 32);
            mma_bf16(S[0], qh4, bh4);
            mma_bf16(S[1], qh4, bh4 + 2);
            mma_bf16(S[0], qh4, bl4);
            mma_bf16(S[1], qh4, bl4 + 2);
            mma_bf16(S[0], ql4, bh4);
            mma_bf16(S[1], ql4, bh4 + 2);
        }

        float mx0 = fmaxf(fmaxf(S[0][0], S[0][1]), fmaxf(S[1][0], S[1][1]));
        float mx1 = fmaxf(fmaxf(S[0][2], S[0][3]), fmaxf(S[1][2], S[1][3]));
        mx0 = fmaxf(mx0, __shfl_xor_sync(0xffffffffu, mx0, 1));
        mx0 = fmaxf(mx0, __shfl_xor_sync(0xffffffffu, mx0, 2));
        mx1 = fmaxf(mx1, __shfl_xor_sync(0xffffffffu, mx1, 1));
        mx1 = fmaxf(mx1, __shfl_xor_sync(0xffffffffu, mx1, 2));
        float mn0 = fmaxf(m0, mx0), mn1 = fmaxf(m1, mx1);
        float f0 = __expf(m0 - mn0), f1 = __expf(m1 - mn1);
        Z0 *= f0; Z1 *= f1;
#pragma unroll
        for (int nt = 0; nt < 8; nt++) {
            O[nt][0] *= f0; O[nt][1] *= f0;
            O[nt][2] *= f1; O[nt][3] *= f1;
        }
        float P00 = __expf(S[0][0] - mn0), P01 = __expf(S[0][1] - mn0);
        float P02 = __expf(S[0][2] - mn1), P03 = __expf(S[0][3] - mn1);
        float P10 = __expf(S[1][0] - mn0), P11 = __expf(S[1][1] - mn0);
        float P12 = __expf(S[1][2] - mn1), P13 = __expf(S[1][3] - mn1);
        Z0 += P00 + P01 + P10 + P11;
        Z1 += P02 + P03 + P12 + P13;
        uint32_t ph[4], pl[4];
        split2(P00, P01, &ph[0], &pl[0]);
        split2(P02, P03, &ph[1], &pl[1]);
        split2(P10, P11, &ph[2], &pl[2]);
        split2(P12, P13, &ph[3], &pl[3]);
        m0 = mn0; m1 = mn1;

#pragma unroll
        for (int hp = 0; hp < 4; hp++) {
            uint32_t vh4[4], vl4[4];
            ldsm_x4t(vh4, khb + v_off + hp * 32);
            ldsm_x4t(vl4, klb + v_off + hp * 32);
            mma_bf16(O[2*hp],     ph, vh4);
            mma_bf16(O[2*hp],     ph, vl4);
            mma_bf16(O[2*hp],     pl, vh4);
            mma_bf16(O[2*hp + 1], ph, vh4 + 2);
            mma_bf16(O[2*hp + 1], ph, vl4 + 2);
            mma_bf16(O[2*hp + 1], pl, vh4 + 2);
        }
        __syncthreads();
    }

    Z0 += __shfl_xor_sync(0xffffffffu, Z0, 1);
    Z0 += __shfl_xor_sync(0xffffffffu, Z0, 2);
    Z1 += __shfl_xor_sync(0xffffffffu, Z1, 1);
    Z1 += __shfl_xor_sync(0xffffffffu, Z1, 2);
    const int r = lane >> 2;
    if ((lane & 3) == 0) {
        mw[warp][r]     = m0;  mw[warp][r + 8] = m1;
        zw[warp][r]     = Z0;  zw[warp][r + 8] = Z1;
    }
    __syncthreads();
    if (t < L_) {
        float M = -1e30f;
#pragma unroll
        for (int w = 0; w < NWARP_; w++) M = fmaxf(M, mw[w][t]);
        Mg[t] = M;
        float Zt = 0.0f;
#pragma unroll
        for (int w = 0; w < NWARP_; w++)
            Zt += zw[w][t] * __expf(mw[w][t] - M);
        int o = (bh * NS_ + split) * L_ + t;
        m_part[o] = M;
        z_part[o] = Zt;
    }
    __syncthreads();
    {
        float g0 = __expf(m0 - Mg[r]);
        float g1 = __expf(m1 - Mg[r + 8]);
        float* cb = (float*)hsm8 + warp * (L_ * HD_);
        int cbase = (lane & 3) * 2;
#pragma unroll
        for (int nt = 0; nt < 8; nt++) {
            int col = nt * 8 + cbase;
            *(float2*)&cb[r * HD_ + col]       = make_float2(O[nt][0] * g0, O[nt][1] * g0);
            *(float2*)&cb[(r + 8) * HD_ + col] = make_float2(O[nt][2] * g1, O[nt][3] * g1);
        }
    }
    __syncthreads();
    {
        const float* call = (const float*)hsm8;
        size_t ob = (size_t)(bh * NS_ + split) * (L_ * HD_);
        for (int i = t; i < L_ * HD_; i += 256) {
            float s = 0.0f;
#pragma unroll
            for (int w = 0; w < NWARP_; w++) s += call[w * (L_ * HD_) + i];
            acc_part[ob + i] = s;
        }
    }
}

__global__ void hop_combine(
    const float* __restrict__ m_part, const float* __restrict__ z_part,
    const float* __restrict__ acc_part, float* __restrict__ qdst, int final_mode)
{
    __shared__ float F[NS_][L_];
    __shared__ float Zs[L_];

    const int bh = blockIdx.x;
    const int b = bh / H_, h = bh % H_;
    const int t = threadIdx.x;

    if (t < L_) {
        float mv[NS_];
        float M = 0.0f;   // softmax_1 clamp at 0
#pragma unroll
        for (int i = 0; i < NS_; i++) {
            mv[i] = m_part[(bh * NS_ + i) * L_ + t];
            M = fmaxf(M, mv[i]);
        }
        float Zt = __expf(-M);   // phantom logit 0
#pragma unroll
        for (int i = 0; i < NS_; i++) {
            float f = __expf(mv[i] - M);
            F[i][t] = f;
            Zt += z_part[(bh * NS_ + i) * L_ + t] * f;
        }
        Zs[t] = Zt;
    }
    __syncthreads();

    for (int idx = t; idx < L_ * HD_; idx += 256) {
        int l = idx >> 6, d = idx & 63;
        float sum = 0.0f;
#pragma unroll
        for (int i = 0; i < NS_; i++)
            sum += acc_part[(size_t)(bh * NS_ + i) * (L_ * HD_) + idx] * F[i][l];
        sum /= Zs[l];
        if (final_mode)
            qdst[((size_t)b * L_ + l) * C_ + h * HD_ + d] = sum;
        else
            qdst[bh * (L_ * HD_) + idx] = sum;
    }
}

// ---------------------------------------------------------------------------
// Launch
// ---------------------------------------------------------------------------
extern "C" void kernel_launch(void* const* d_in, const int* in_sizes, int n_in,
                              void* d_out, int out_size)
{
    const float* x     = (const float*)d_in[0];
    const float* query = (const float*)d_in[1];
    const float* Wq    = (const float*)d_in[2];
    const float* Wk    = (const float*)d_in[3];
    const float* Wv    = (const float*)d_in[4];
    const float* Wproj = (const float*)d_in[5];
    const float* bproj = (const float*)d_in[6];
    float* out = (float*)d_out;

    float *q0_scr, *qf_scr, *tmp_scr, *q_state, *m_part, *z_part, *acc_part;
    __nv_bfloat16 *xh, *xl, *wh, *wl, *khg, *klg;
    cudaGetSymbolAddress((void**)&q0_scr, g_q0_scr);
    cudaGetSymbolAddress((void**)&qf_scr, g_qf_scr);
    cudaGetSymbolAddress((void**)&tmp_scr, g_tmp_scr);
    cudaGetSymbolAddress((void**)&q_state, g_q_state);
    cudaGetSymbolAddress((void**)&m_part, g_m_part);
    cudaGetSymbolAddress((void**)&z_part, g_z_part);
    cudaGetSymbolAddress((void**)&acc_part, g_acc_part);
    cudaGetSymbolAddress((void**)&xh, g_xh);
    cudaGetSymbolAddress((void**)&xl, g_xl);
    cudaGetSymbolAddress((void**)&wh, g_wh);
    cudaGetSymbolAddress((void**)&wl, g_wl);
    cudaGetSymbolAddress((void**)&khg, g_kh);
    cudaGetSymbolAddress((void**)&klg, g_kl);

    static bool attr_set = false;
    if (!attr_set) {
        cudaFuncSetAttribute(k_gemm_mma, cudaFuncAttributeMaxDynamicSharedMemorySize,
                             GEMM_SMEM_REQ);
        cudaFuncSetAttribute(hop_partial, cudaFuncAttributeMaxDynamicSharedMemorySize,
                             HOP_SMEM_);
        attr_set = true;
    }

    // split/convert x and Wk into row-major bf16 hi/lo
    {
        int nch_x = (MROWS_ * C_) / 8;
        convert_split_kernel<<<(nch_x + 255) / 256, 256>>>(x, xh, xl, nch_x);
        int nch_w = (C_ * C_) / 8;
        convert_split_kernel<<<(nch_w + 255) / 256, 256>>>(Wk, wh, wl, nch_w);
    }
    // q0 = query @ Wq^T
    small_gemm_nt<<<dim3(C_ / 64, 1), 256>>>(query, Wq, nullptr, q0_scr, L_, C_, C_);
    // k = x @ Wk^T via HMMA -> kh/kl bf16 head-major
    k_gemm_mma<<<dim3(C_ / 128, MROWS_ / 128), GT_, GEMM_SMEM_REQ>>>(xh, xl, wh, wl, khg, klg);
    // 3-step Hopfield attention (HMMA flash)
    hop_init_q<<<BH_, 256>>>(q0_scr, q_state);
    for (int s = 0; s < STEPS_; s++) {
        hop_partial<<<dim3(NS_, BH_), 256, HOP_SMEM_>>>(
            q_state, khg, klg, m_part, z_part, acc_part);
        hop_combine<<<BH_, 256>>>(m_part, z_part, acc_part,
                                  (s == STEPS_ - 1) ? qf_scr : q_state,
                                  (s == STEPS_ - 1) ? 1 : 0);
    }
    // out projections
    small_gemm_nt<<<dim3(C_ / 64, (B_ * L_) / 16), 256>>>(
        qf_scr, Wv, nullptr, tmp_scr, B_ * L_, C_, C_);
    small_gemm_nt<<<dim3(C_ / 64, (B_ * L_) / 16), 256>>>(
        tmp_scr, Wproj, bproj, out, B_ * L_, C_, C_);
}

// round 9
// speedup vs baseline: 6.9275x; 1.2560x over previous
#include <cuda_runtime.h>
#include <cuda_bf16.h>
#include <cuda_fp16.h>
#include <cstdint>

// ---------------------------------------------------------------------------
// Shapes (fixed by the problem)
// ---------------------------------------------------------------------------
#define B_  16
#define N_  4096
#define C_  768
#define L_  16
#define H_  12
#define HD_ 64
#define STEPS_ 3
#define BH_ (B_ * H_)               // 192

#define MROWS_ (B_ * N_)            // 65536
#define KSEG_  2                    // xh*wh, xl*wh  (fp16 2-term)
#define BK_    64
#define CH_PER_SEG_ (C_ / BK_)      // 12
#define NCHUNK_TOT_ (KSEG_ * CH_PER_SEG_)  // 24

// Hopfield split
#define TN_ 128
#define NWARP_ 8
#define NS_ 4
#define NT_SPL_ (N_ / NS_ / TN_)    // 8 tiles per split

// ---------------------------------------------------------------------------
// Scratch (__device__ globals)
// ---------------------------------------------------------------------------
__device__ __align__(16) __nv_bfloat16 g_kh[(size_t)BH_ * N_ * HD_];
__device__ __align__(16) __nv_bfloat16 g_kl[(size_t)BH_ * N_ * HD_];
__device__ __align__(16) __half g_xh16[(size_t)MROWS_ * C_];
__device__ __align__(16) __half g_xl16[(size_t)MROWS_ * C_];
__device__ __align__(16) __half g_wh16[(size_t)C_ * C_];
__device__ float g_q0_scr[L_ * C_];
__device__ float g_qf_scr[B_ * L_ * C_];
__device__ float g_tmp_scr[B_ * L_ * C_];
__device__ __align__(16) float g_q_state[BH_ * L_ * HD_];
__device__ float g_m_part[BH_ * NS_ * L_];
__device__ float g_z_part[BH_ * NS_ * L_];
__device__ __align__(16) float g_acc_part[(size_t)BH_ * NS_ * L_ * HD_];

// ---------------------------------------------------------------------------
// helpers
// ---------------------------------------------------------------------------
__device__ __forceinline__ uint32_t smem_u32(const void* p) {
    uint32_t a;
    asm("{ .reg .u64 t; cvta.to.shared.u64 t, %1; cvt.u32.u64 %0, t; }" : "=r"(a) : "l"(p));
    return a;
}
__device__ __forceinline__ void cpa16(uint32_t dst, const void* src) {
    asm volatile("cp.async.cg.shared.global [%0], [%1], 16;" :: "r"(dst), "l"(src));
}
#define CP_COMMIT() asm volatile("cp.async.commit_group;" ::: "memory")
#define CP_WAIT1()  asm volatile("cp.async.wait_group 1;" ::: "memory")
#define CP_WAIT0()  asm volatile("cp.async.wait_group 0;" ::: "memory")

__device__ __forceinline__ void ldsm_x4(uint32_t* r, uint32_t addr) {
    asm volatile("ldmatrix.sync.aligned.m8n8.x4.shared.b16 {%0,%1,%2,%3}, [%4];"
                 : "=r"(r[0]), "=r"(r[1]), "=r"(r[2]), "=r"(r[3]) : "r"(addr));
}
__device__ __forceinline__ void ldsm_x4t(uint32_t* r, uint32_t addr) {
    asm volatile("ldmatrix.sync.aligned.m8n8.x4.trans.shared.b16 {%0,%1,%2,%3}, [%4];"
                 : "=r"(r[0]), "=r"(r[1]), "=r"(r[2]), "=r"(r[3]) : "r"(addr));
}
__device__ __forceinline__ void mma_bf16(float* d, const uint32_t* a, const uint32_t* b) {
    asm volatile(
        "mma.sync.aligned.m16n8k16.row.col.f32.bf16.bf16.f32 "
        "{%0,%1,%2,%3}, {%4,%5,%6,%7}, {%8,%9}, {%0,%1,%2,%3};"
        : "+f"(d[0]), "+f"(d[1]), "+f"(d[2]), "+f"(d[3])
        : "r"(a[0]), "r"(a[1]), "r"(a[2]), "r"(a[3]), "r"(b[0]), "r"(b[1]));
}
__device__ __forceinline__ void mma_fp16(float* d, const uint32_t* a, const uint32_t* b) {
    asm volatile(
        "mma.sync.aligned.m16n8k16.row.col.f32.f16.f16.f32 "
        "{%0,%1,%2,%3}, {%4,%5,%6,%7}, {%8,%9}, {%0,%1,%2,%3};"
        : "+f"(d[0]), "+f"(d[1]), "+f"(d[2]), "+f"(d[3])
        : "r"(a[0]), "r"(a[1]), "r"(a[2]), "r"(a[3]), "r"(b[0]), "r"(b[1]));
}
__device__ __forceinline__ void split2(float a, float b, uint32_t* hi, uint32_t* lo) {
    __nv_bfloat16 ha = __float2bfloat16(a), hb = __float2bfloat16(b);
    __nv_bfloat16 la = __float2bfloat16(a - __bfloat162float(ha));
    __nv_bfloat16 lb = __float2bfloat16(b - __bfloat162float(hb));
    *hi = (uint32_t)__bfloat16_as_ushort(ha) | ((uint32_t)__bfloat16_as_ushort(hb) << 16);
    *lo = (uint32_t)__bfloat16_as_ushort(la) | ((uint32_t)__bfloat16_as_ushort(lb) << 16);
}
__device__ __forceinline__ void split2h(float a, float b, uint32_t* hi, uint32_t* lo) {
    __half ha = __float2half(a), hb = __float2half(b);
    __half la = __float2half(a - __half2float(ha));
    __half lb = __float2half(b - __half2float(hb));
    *hi = (uint32_t)__half_as_ushort(ha) | ((uint32_t)__half_as_ushort(hb) << 16);
    *lo = (uint32_t)__half_as_ushort(la) | ((uint32_t)__half_as_ushort(lb) << 16);
}

// ---------------------------------------------------------------------------
// Kernel A1: split fp32 -> (hi, lo) fp16 pair (for x)
// ---------------------------------------------------------------------------
__global__ void __launch_bounds__(256) convert_split_fp16(
    const float* __restrict__ src, __half* __restrict__ hi,
    __half* __restrict__ lo, int nchunks)
{
    int idx = blockIdx.x * 256 + threadIdx.x;
    if (idx >= nchunks) return;
    size_t e = (size_t)idx * 8;

    const float4* p = (const float4*)(src + e);
    float4 a = p[0], b = p[1];
    float v[8] = {a.x, a.y, a.z, a.w, b.x, b.y, b.z, b.w};

    uint32_t hp[4], lp[4];
#pragma unroll
    for (int i = 0; i < 4; i++) split2h(v[2*i], v[2*i+1], &hp[i], &lp[i]);
    *(uint4*)(hi + e) = make_uint4(hp[0], hp[1], hp[2], hp[3]);
    *(uint4*)(lo + e) = make_uint4(lp[0], lp[1], lp[2], lp[3]);
}

// Kernel A2: fp32 -> fp16 (for W)
__global__ void __launch_bounds__(256) convert_fp16(
    const float* __restrict__ src, __half* __restrict__ dst, int nchunks)
{
    int idx = blockIdx.x * 256 + threadIdx.x;
    if (idx >= nchunks) return;
    size_t e = (size_t)idx * 8;
    const float4* p = (const float4*)(src + e);
    float4 a = p[0], b = p[1];
    float v[8] = {a.x, a.y, a.z, a.w, b.x, b.y, b.z, b.w};
    uint32_t o[4];
#pragma unroll
    for (int i = 0; i < 4; i++) {
        __half h0 = __float2half(v[2*i]), h1 = __float2half(v[2*i+1]);
        o[i] = (uint32_t)__half_as_ushort(h0) | ((uint32_t)__half_as_ushort(h1) << 16);
    }
    *(uint4*)(dst + e) = make_uint4(o[0], o[1], o[2], o[3]);
}

// ---------------------------------------------------------------------------
// Kernel B: HMMA GEMM  k = X @ Wk^T  (K = 2*768, fp16 2-term)
// CTA 128x128 with 4 warps of 64x64, BK=64, 3-stage cp.async, XOR swizzle,
// 2 CTAs/SM, fragment double-buffering. Emits kh/kl bf16 head-major.
// ---------------------------------------------------------------------------
#define KTB_ 16384
#define STAGEB_ (2 * KTB_)
#define NSTG_ 3
#define GEMM_SMEM_REQ (NSTG_ * STAGEB_)  // 98304
#define GT_ 128

__device__ __forceinline__ void load_tile64(
    uint32_t aS, uint32_t bS, const char* Aseg, const char* Bseg,
    int mt, int nt, int kk, int tid)
{
#pragma unroll
    for (int i = 0; i < 8; i++) {
        int idx = tid + i * GT_;
        int row = idx >> 3, c = idx & 7;
        uint32_t sw = (uint32_t)((c ^ (row & 7)) * 16);
        cpa16(aS + row * 128 + sw,
              Aseg + ((size_t)(mt * 128 + row) * C_ + kk + c * 8) * 2);
    }
#pragma unroll
    for (int i = 0; i < 8; i++) {
        int idx = tid + i * GT_;
        int row = idx >> 3, c = idx & 7;
        uint32_t sw = (uint32_t)((c ^ (row & 7)) * 16);
        cpa16(bS + row * 128 + sw,
              Bseg + ((size_t)(nt * 128 + row) * C_ + kk + c * 8) * 2);
    }
}

struct Frag { uint32_t a[4][4]; uint32_t b[4][4]; };

__device__ __forceinline__ void load_frag(
    Frag& f, uint32_t aS, uint32_t bS, int h,
    int wm, int wn, int arow_l, int agrp_l, int brow_l, int bgrp_l)
{
#pragma unroll
    for (int mi = 0; mi < 4; mi++) {
        int row = wm * 64 + mi * 16 + arow_l;
        int g   = (2 * h + agrp_l) ^ (row & 7);
        ldsm_x4(f.a[mi], aS + row * 128 + g * 16);
    }
#pragma unroll
    for (int p = 0; p < 4; p++) {
        int row = wn * 64 + p * 16 + brow_l;
        int g   = (2 * h + bgrp_l) ^ (row & 7);
        ldsm_x4(f.b[p], bS + row * 128 + g * 16);
    }
}

__global__ void __launch_bounds__(GT_, 2) k_gemm_mma(
    const __half* __restrict__ xh, const __half* __restrict__ xl,
    const __half* __restrict__ wh,
    __nv_bfloat16* __restrict__ khg, __nv_bfloat16* __restrict__ klg)
{
    extern __shared__ char dsm[];
    const uint32_t sbase = smem_u32(dsm);

    const int tid  = threadIdx.x;
    const int lane = tid & 31;
    const int warp = tid >> 5;
    const int wm   = warp >> 1;
    const int wn   = warp & 1;
    const int nt   = blockIdx.x;
    const int mt   = blockIdx.y;

    const char* Asrc[KSEG_] = {(const char*)xh, (const char*)xl};
    const char* Bsrc[KSEG_] = {(const char*)wh, (const char*)wh};

    float acc[4][8][4];
#pragma unroll
    for (int mi = 0; mi < 4; mi++)
#pragma unroll
        for (int ni = 0; ni < 8; ni++)
#pragma unroll
            for (int i = 0; i < 4; i++) acc[mi][ni][i] = 0.0f;

#pragma unroll
    for (int s = 0; s < NSTG_ - 1; s++) {
        load_tile64(sbase + s * STAGEB_, sbase + s * STAGEB_ + KTB_,
                    Asrc[0], Bsrc[0], mt, nt, s * BK_, tid);
        CP_COMMIT();
    }

    const int arow_l = lane & 15;
    const int agrp_l = lane >> 4;
    const int brow_l = (lane & 7) + ((lane >> 4) & 1) * 8;
    const int bgrp_l = (lane >> 3) & 1;

    Frag fr[2];

    for (int kc = 0; kc < NCHUNK_TOT_; kc++) {
        CP_WAIT1();
        __syncthreads();

        int pf = kc + NSTG_ - 1;
        if (pf < NCHUNK_TOT_) {
            int seg = pf / CH_PER_SEG_;
            int kk  = (pf % CH_PER_SEG_) * BK_;
            int s   = pf % NSTG_;
            load_tile64(sbase + s * STAGEB_, sbase + s * STAGEB_ + KTB_,
                        Asrc[seg], Bsrc[seg], mt, nt, kk, tid);
        }
        CP_COMMIT();

        const uint32_t aS = sbase + (kc % NSTG_) * STAGEB_;
        const uint32_t bS = aS + KTB_;

        load_frag(fr[0], aS, bS, 0, wm, wn, arow_l, agrp_l, brow_l, bgrp_l);
#pragma unroll
        for (int h = 0; h < 4; h++) {
            if (h < 3)
                load_frag(fr[(h + 1) & 1], aS, bS, h + 1,
                          wm, wn, arow_l, agrp_l, brow_l, bgrp_l);
            const Frag& f = fr[h & 1];
#pragma unroll
            for (int mi = 0; mi < 4; mi++)
#pragma unroll
                for (int ni = 0; ni < 8; ni++)
                    mma_fp16(acc[mi][ni], f.a[mi], f.b[ni >> 1] + (ni & 1) * 2);
        }
    }

    // epilogue: split to bf16 hi/lo, scatter head-major [B, H, N, 64]
#pragma unroll
    for (int mi = 0; mi < 4; mi++) {
#pragma unroll
        for (int ni = 0; ni < 8; ni++) {
            int r = mt * 128 + wm * 64 + mi * 16 + (lane >> 2);
            int c = nt * 128 + wn * 64 + ni * 8 + (lane & 3) * 2;
            int b = r >> 12, n = r & (N_ - 1);
            int hh = c >> 6, d = c & 63;
            size_t addr = (((size_t)b * H_ + hh) * N_ + n) * HD_ + d;
            uint32_t h01, l01, h23, l23;
            split2(acc[mi][ni][0], acc[mi][ni][1], &h01, &l01);
            split2(acc[mi][ni][2], acc[mi][ni][3], &h23, &l23);
            *(uint32_t*)&khg[addr] = h01;
            *(uint32_t*)&klg[addr] = l01;
            *(uint32_t*)&khg[addr + 8 * HD_] = h23;
            *(uint32_t*)&klg[addr + 8 * HD_] = l23;
        }
    }
}

// ---------------------------------------------------------------------------
// Kernel 2: small GEMM  C[M,N] = A[M,K]*B[N,K]^T (+bias), BK=64
// ---------------------------------------------------------------------------
__global__ void __launch_bounds__(256) small_gemm_nt(
    const float* __restrict__ A, const float* __restrict__ Bm,
    const float* __restrict__ bias, float* __restrict__ C,
    int M, int N, int K)
{
    __shared__ float AsT[64][17];
    __shared__ float BsT[64][65];

    const int t  = threadIdx.x;
    const int n0 = blockIdx.x * 64;
    const int m0 = blockIdx.y * 16;
    const int r0 = t >> 6;   // 0..3
    const int c  = t & 63;

    float acc[4] = {0.f, 0.f, 0.f, 0.f};

    for (int k0 = 0; k0 < K; k0 += 64) {
        __syncthreads();
        {   // A tile 16x64 -> transposed; one float4 per thread
            int mm = t >> 4, k4 = (t & 15) * 4;
            float4 v = *(const float4*)&A[(long)(m0 + mm) * K + k0 + k4];
            AsT[k4 + 0][mm] = v.x; AsT[k4 + 1][mm] = v.y;
            AsT[k4 + 2][mm] = v.z; AsT[k4 + 3][mm] = v.w;
        }
        {   // B tile 64x64 -> transposed; four float4 per thread
#pragma unroll
            for (int i = 0; i < 4; i++) {
                int idx = t + i * 256;
                int nn = idx >> 4, k4 = (idx & 15) * 4;
                float4 v = *(const float4*)&Bm[(long)(n0 + nn) * K + k0 + k4];
                BsT[k4 + 0][nn] = v.x; BsT[k4 + 1][nn] = v.y;
                BsT[k4 + 2][nn] = v.z; BsT[k4 + 3][nn] = v.w;
            }
        }
        __syncthreads();
#pragma unroll
        for (int kk = 0; kk < 64; kk++) {
            float bb = BsT[kk][c];
            acc[0] = fmaf(AsT[kk][r0 +  0], bb, acc[0]);
            acc[1] = fmaf(AsT[kk][r0 +  4], bb, acc[1]);
            acc[2] = fmaf(AsT[kk][r0 +  8], bb, acc[2]);
            acc[3] = fmaf(AsT[kk][r0 + 12], bb, acc[3]);
        }
    }
    float bv = bias ? bias[n0 + c] : 0.0f;
#pragma unroll
    for (int i = 0; i < 4; i++)
        C[(long)(m0 + r0 + 4 * i) * N + n0 + c] = acc[i] + bv;
}

// ---------------------------------------------------------------------------
// Hopfield step via HMMA (flash-attn v2 structure), split-N. (unchanged)
// ---------------------------------------------------------------------------
__global__ void hop_init_q(const float* __restrict__ q0, float* __restrict__ qst)
{
    int bh = blockIdx.x, h = bh % H_;
    for (int i = threadIdx.x; i < L_ * HD_; i += 256) {
        int l = i >> 6, d = i & 63;
        qst[bh * (L_ * HD_) + i] = q0[l * C_ + h * HD_ + d];
    }
}

#define KROW_ 144
#define KTILE_PAD_ (128 * KROW_)
#define HOP_SMEM_ (4 * KTILE_PAD_ + 2 * L_ * KROW_)   // 78336

__global__ void __launch_bounds__(256, 2) hop_partial(
    const float* __restrict__ qst,
    const __nv_bfloat16* __restrict__ khg, const __nv_bfloat16* __restrict__ klg,
    float* __restrict__ m_part, float* __restrict__ z_part,
    float* __restrict__ acc_part)
{
    extern __shared__ __align__(16) char hsm8[];
    __shared__ float mw[NWARP_][L_];
    __shared__ float zw[NWARP_][L_];
    __shared__ float Mg[L_];

    const int t     = threadIdx.x;
    const int warp  = t >> 5;
    const int lane  = t & 31;
    const int split = blockIdx.x;
    const int bh    = blockIdx.y;
    const uint32_t sb  = smem_u32(hsm8);
    const uint32_t KH0 = sb;
    const uint32_t KL0 = sb + 2 * KTILE_PAD_;
    const uint32_t QHo = sb + 4 * KTILE_PAD_;
    const uint32_t QLo = QHo + L_ * KROW_;

    const char* ksrc_h = (const char*)(khg + ((size_t)bh * N_ + split * (N_ / NS_)) * HD_);
    const char* ksrc_l = (const char*)(klg + ((size_t)bh * N_ + split * (N_ / NS_)) * HD_);

#pragma unroll
    for (int i = 0; i < 4; i++) {
        int idx = t + i * 256;
        int row = idx >> 3, c = idx & 7;
        cpa16(KH0 + row * KROW_ + c * 16, ksrc_h + (size_t)idx * 16);
        cpa16(KL0 + row * KROW_ + c * 16, ksrc_l + (size_t)idx * 16);
    }
    CP_COMMIT();

    {
        float4 v = ((const float4*)(qst + bh * (L_ * HD_)))[t];
        int e = t * 4, r = e >> 6, d = e & 63;
        uint32_t h01, l01, h23, l23;
        split2(v.x * 0.125f, v.y * 0.125f, &h01, &l01);
        split2(v.z * 0.125f, v.w * 0.125f, &h23, &l23);
        char* qh = hsm8 + 4 * KTILE_PAD_ + r * KROW_ + d * 2;
        char* ql = qh + L_ * KROW_;
        *(uint32_t*)qh = h01; *(uint32_t*)(qh + 4) = h23;
        *(uint32_t*)ql = l01; *(uint32_t*)(ql + 4) = l23;
    }

    float S[2][4], O[8][4];
#pragma unroll
    for (int i = 0; i < 8; i++)
#pragma unroll
        for (int j = 0; j < 4; j++) O[i][j] = 0.0f;
    float m0 = -1e30f, m1 = -1e30f, Z0 = 0.0f, Z1 = 0.0f;

    const uint32_t qa_off = (uint32_t)((lane & 15) * KROW_ + (lane >> 4) * 16);
    const uint32_t kb_off = (uint32_t)((warp * 16 + ((lane >> 4) & 1) * 8 + (lane & 7)) * KROW_
                                       + ((lane >> 3) & 1) * 16);
    const uint32_t v_off  = (uint32_t)((warp * 16 + (lane & 15)) * KROW_ + (lane >> 4) * 16);

    for (int tile = 0; tile < NT_SPL_; tile++) {
        if (tile + 1 < NT_SPL_) {
            uint32_t khd = KH0 + ((tile + 1) & 1) * KTILE_PAD_;
            uint32_t kld = KL0 + ((tile + 1) & 1) * KTILE_PAD_;
            const char* sh = ksrc_h + (size_t)(tile + 1) * (TN_ * HD_ * 2);
            const char* sl = ksrc_l + (size_t)(tile + 1) * (TN_ * HD_ * 2);
#pragma unroll
            for (int i = 0; i < 4; i++) {
                int idx = t + i * 256;
                int row = idx >> 3, c = idx & 7;
                cpa16(khd + row * KROW_ + c * 16, sh + (size_t)idx * 16);
                cpa16(kld + row * KROW_ + c * 16, sl + (size_t)idx * 16);
            }
            CP_COMMIT();
            CP_WAIT1();
        } else {
            CP_WAIT0();
        }
        __syncthreads();

        const uint32_t khb = KH0 + (tile & 1) * KTILE_PAD_;
        const uint32_t klb = KL0 + (tile & 1) * KTILE_PAD_;

#pragma unroll
        for (int nt = 0; nt < 2; nt++)
#pragma unroll
            for (int i = 0; i < 4; i++) S[nt][i] = 0.0f;
#pragma unroll
        for (int kc = 0; kc < 4; kc++) {
            uint32_t qh4[4], ql4[4], bh4[4], bl4[4];
            ldsm_x4(qh4, QHo + qa_off + kc * 32);
            ldsm_x4(ql4, QLo + qa_off + kc * 32);
            ldsm_x4(bh4, khb + kb_off + kc * 32);
            ldsm_x4(bl4, klb + kb_off + kc * 32);
            mma_bf16(S[0], qh4, bh4);
            mma_bf16(S[1], qh4, bh4 + 2);
            mma_bf16(S[0], qh4, bl4);
            mma_bf16(S[1], qh4, bl4 + 2);
            mma_bf16(S[0], ql4, bh4);
            mma_bf16(S[1], ql4, bh4 + 2);
        }

        float mx0 = fmaxf(fmaxf(S[0][0], S[0][1]), fmaxf(S[1][0], S[1][1]));
        float mx1 = fmaxf(fmaxf(S[0][2], S[0][3]), fmaxf(S[1][2], S[1][3]));
        mx0 = fmaxf(mx0, __shfl_xor_sync(0xffffffffu, mx0, 1));
        mx0 = fmaxf(mx0, __shfl_xor_sync(0xffffffffu, mx0, 2));
        mx1 = fmaxf(mx1, __shfl_xor_sync(0xffffffffu, mx1, 1));
        mx1 = fmaxf(mx1, __shfl_xor_sync(0xffffffffu, mx1, 2));
        float mn0 = fmaxf(m0, mx0), mn1 = fmaxf(m1, mx1);
        float f0 = __expf(m0 - mn0), f1 = __expf(m1 - mn1);
        Z0 *= f0; Z1 *= f1;
#pragma unroll
        for (int nt = 0; nt < 8; nt++) {
            O[nt][0] *= f0; O[nt][1] *= f0;
            O[nt][2] *= f1; O[nt][3] *= f1;
        }
        float P00 = __expf(S[0][0] - mn0), P01 = __expf(S[0][1] - mn0);
        float P02 = __expf(S[0][2] - mn1), P03 = __expf(S[0][3] - mn1);
        float P10 = __expf(S[1][0] - mn0), P11 = __expf(S[1][1] - mn0);
        float P12 = __expf(S[1][2] - mn1), P13 = __expf(S[1][3] - mn1);
        Z0 += P00 + P01 + P10 + P11;
        Z1 += P02 + P03 + P12 + P13;
        uint32_t ph[4], pl[4];
        split2(P00, P01, &ph[0], &pl[0]);
        split2(P02, P03, &ph[1], &pl[1]);
        split2(P10, P11, &ph[2], &pl[2]);
        split2(P12, P13, &ph[3], &pl[3]);
        m0 = mn0; m1 = mn1;

#pragma unroll
        for (int hp = 0; hp < 4; hp++) {
            uint32_t vh4[4], vl4[4];
            ldsm_x4t(vh4, khb + v_off + hp * 32);
            ldsm_x4t(vl4, klb + v_off + hp * 32);
            mma_bf16(O[2*hp],     ph, vh4);
            mma_bf16(O[2*hp],     ph, vl4);
            mma_bf16(O[2*hp],     pl, vh4);
            mma_bf16(O[2*hp + 1], ph, vh4 + 2);
            mma_bf16(O[2*hp + 1], ph, vl4 + 2);
            mma_bf16(O[2*hp + 1], pl, vh4 + 2);
        }
        __syncthreads();
    }

    Z0 += __shfl_xor_sync(0xffffffffu, Z0, 1);
    Z0 += __shfl_xor_sync(0xffffffffu, Z0, 2);
    Z1 += __shfl_xor_sync(0xffffffffu, Z1, 1);
    Z1 += __shfl_xor_sync(0xffffffffu, Z1, 2);
    const int r = lane >> 2;
    if ((lane & 3) == 0) {
        mw[warp][r]     = m0;  mw[warp][r + 8] = m1;
        zw[warp][r]     = Z0;  zw[warp][r + 8] = Z1;
    }
    __syncthreads();
    if (t < L_) {
        float M = -1e30f;
#pragma unroll
        for (int w = 0; w < NWARP_; w++) M = fmaxf(M, mw[w][t]);
        Mg[t] = M;
        float Zt = 0.0f;
#pragma unroll
        for (int w = 0; w < NWARP_; w++)
            Zt += zw[w][t] * __expf(mw[w][t] - M);
        int o = (bh * NS_ + split) * L_ + t;
        m_part[o] = M;
        z_part[o] = Zt;
    }
    __syncthreads();
    {
        float g0 = __expf(m0 - Mg[r]);
        float g1 = __expf(m1 - Mg[r + 8]);
        float* cb = (float*)hsm8 + warp * (L_ * HD_);
        int cbase = (lane & 3) * 2;
#pragma unroll
        for (int nt = 0; nt < 8; nt++) {
            int col = nt * 8 + cbase;
            *(float2*)&cb[r * HD_ + col]       = make_float2(O[nt][0] * g0, O[nt][1] * g0);
            *(float2*)&cb[(r + 8) * HD_ + col] = make_float2(O[nt][2] * g1, O[nt][3] * g1);
        }
    }
    __syncthreads();
    {
        const float* call = (const float*)hsm8;
        size_t ob = (size_t)(bh * NS_ + split) * (L_ * HD_);
        for (int i = t; i < L_ * HD_; i += 256) {
            float s = 0.0f;
#pragma unroll
            for (int w = 0; w < NWARP_; w++) s += call[w * (L_ * HD_) + i];
            acc_part[ob + i] = s;
        }
    }
}

__global__ void hop_combine(
    const float* __restrict__ m_part, const float* __restrict__ z_part,
    const float* __restrict__ acc_part, float* __restrict__ qdst, int final_mode)
{
    __shared__ float F[NS_][L_];
    __shared__ float Zs[L_];

    const int bh = blockIdx.x;
    const int b = bh / H_, h = bh % H_;
    const int t = threadIdx.x;

    if (t < L_) {
        float mv[NS_];
        float M = 0.0f;   // softmax_1 clamp at 0
#pragma unroll
        for (int i = 0; i < NS_; i++) {
            mv[i] = m_part[(bh * NS_ + i) * L_ + t];
            M = fmaxf(M, mv[i]);
        }
        float Zt = __expf(-M);   // phantom logit 0
#pragma unroll
        for (int i = 0; i < NS_; i++) {
            float f = __expf(mv[i] - M);
            F[i][t] = f;
            Zt += z_part[(bh * NS_ + i) * L_ + t] * f;
        }
        Zs[t] = Zt;
    }
    __syncthreads();

    for (int idx = t; idx < L_ * HD_; idx += 256) {
        int l = idx >> 6, d = idx & 63;
        float sum = 0.0f;
#pragma unroll
        for (int i = 0; i < NS_; i++)
            sum += acc_part[(size_t)(bh * NS_ + i) * (L_ * HD_) + idx] * F[i][l];
        sum /= Zs[l];
        if (final_mode)
            qdst[((size_t)b * L_ + l) * C_ + h * HD_ + d] = sum;
        else
            qdst[bh * (L_ * HD_) + idx] = sum;
    }
}

// ---------------------------------------------------------------------------
// Launch
// ---------------------------------------------------------------------------
extern "C" void kernel_launch(void* const* d_in, const int* in_sizes, int n_in,
                              void* d_out, int out_size)
{
    const float* x     = (const float*)d_in[0];
    const float* query = (const float*)d_in[1];
    const float* Wq    = (const float*)d_in[2];
    const float* Wk    = (const float*)d_in[3];
    const float* Wv    = (const float*)d_in[4];
    const float* Wproj = (const float*)d_in[5];
    const float* bproj = (const float*)d_in[6];
    float* out = (float*)d_out;

    float *q0_scr, *qf_scr, *tmp_scr, *q_state, *m_part, *z_part, *acc_part;
    __half *xh, *xl, *wh;
    __nv_bfloat16 *khg, *klg;
    cudaGetSymbolAddress((void**)&q0_scr, g_q0_scr);
    cudaGetSymbolAddress((void**)&qf_scr, g_qf_scr);
    cudaGetSymbolAddress((void**)&tmp_scr, g_tmp_scr);
    cudaGetSymbolAddress((void**)&q_state, g_q_state);
    cudaGetSymbolAddress((void**)&m_part, g_m_part);
    cudaGetSymbolAddress((void**)&z_part, g_z_part);
    cudaGetSymbolAddress((void**)&acc_part, g_acc_part);
    cudaGetSymbolAddress((void**)&xh, g_xh16);
    cudaGetSymbolAddress((void**)&xl, g_xl16);
    cudaGetSymbolAddress((void**)&wh, g_wh16);
    cudaGetSymbolAddress((void**)&khg, g_kh);
    cudaGetSymbolAddress((void**)&klg, g_kl);

    static bool attr_set = false;
    if (!attr_set) {
        cudaFuncSetAttribute(k_gemm_mma, cudaFuncAttributeMaxDynamicSharedMemorySize,
                             GEMM_SMEM_REQ);
        cudaFuncSetAttribute(hop_partial, cudaFuncAttributeMaxDynamicSharedMemorySize,
                             HOP_SMEM_);
        attr_set = true;
    }

    // convert: x -> fp16 hi/lo pair; Wk -> fp16
    {
        int nch_x = (MROWS_ * C_) / 8;
        convert_split_fp16<<<(nch_x + 255) / 256, 256>>>(x, xh, xl, nch_x);
        int nch_w = (C_ * C_) / 8;
        convert_fp16<<<(nch_w + 255) / 256, 256>>>(Wk, wh, nch_w);
    }
    // q0 = query @ Wq^T
    small_gemm_nt<<<dim3(C_ / 64, 1), 256>>>(query, Wq, nullptr, q0_scr, L_, C_, C_);
    // k = x @ Wk^T via fp16 HMMA 2-term -> kh/kl bf16 head-major
    k_gemm_mma<<<dim3(C_ / 128, MROWS_ / 128), GT_, GEMM_SMEM_REQ>>>(xh, xl, wh, khg, klg);
    // 3-step Hopfield attention (HMMA flash)
    hop_init_q<<<BH_, 256>>>(q0_scr, q_state);
    for (int s = 0; s < STEPS_; s++) {
        hop_partial<<<dim3(NS_, BH_), 256, HOP_SMEM_>>>(
            q_state, khg, klg, m_part, z_part, acc_part);
        hop_combine<<<BH_, 256>>>(m_part, z_part, acc_part,
                                  (s == STEPS_ - 1) ? qf_scr : q_state,
                                  (s == STEPS_ - 1) ? 1 : 0);
    }
    // out projections
    small_gemm_nt<<<dim3(C_ / 64, (B_ * L_) / 16), 256>>>(
        qf_scr, Wv, nullptr, tmp_scr, B_ * L_, C_, C_);
    small_gemm_nt<<<dim3(C_ / 64, (B_ * L_) / 16), 256>>>(
        tmp_scr, Wproj, bproj, out, B_ * L_, C_, C_);
}